// round 6
// baseline (speedup 1.0000x reference)
#include <cuda_runtime.h>
#include <cuda_bf16.h>
#include <math.h>
#include <stdint.h>

// ---------------------------------------------------------------------------
// MiniGPT forward. B=2 T=2048 D=256 H=4 DK=64 DFF=1024 L=4 V=32000
// GEMMs: mma.sync bf16x3 compensated split. Attention: fp32 flash with
// FMA-polynomial exp2 (MUFU was the bottleneck) and 256-block grid.
// ---------------------------------------------------------------------------

#define Tn    2048
#define Bn    2
#define Dn    256
#define Mrows 4096

// fp32 scratch
__device__ float g_x[Mrows * Dn];
__device__ float g_qkv[Mrows * 3 * Dn];
__device__ float g_tmp[Mrows * Dn];

// bf16 hi/lo activations (D-wide) and MLP hidden (DFF-wide)
__device__ __nv_bfloat16 g_acth[Mrows * Dn],  g_actl[Mrows * Dn];
__device__ __nv_bfloat16 g_hh[Mrows * 1024],  g_hl[Mrows * 1024];

// bf16 hi/lo weights
__device__ __nv_bfloat16 g_wqkv_h[4 * 768 * 256],  g_wqkv_l[4 * 768 * 256];
__device__ __nv_bfloat16 g_wfc_h [4 * 256 * 256],  g_wfc_l [4 * 256 * 256];
__device__ __nv_bfloat16 g_w1_h  [4 * 1024 * 256], g_w1_l  [4 * 1024 * 256];
__device__ __nv_bfloat16 g_w2_h  [4 * 256 * 1024], g_w2_l  [4 * 256 * 1024];
__device__ __nv_bfloat16 g_wout_h[32000 * 256],    g_wout_l[32000 * 256];

// ---------------------------------------------------------------------------
// PTX helpers
// ---------------------------------------------------------------------------
__device__ __forceinline__ uint32_t smem_to_u32(const void* p) {
    uint32_t a;
    asm("{ .reg .u64 t; cvta.to.shared.u64 t, %1; cvt.u32.u64 %0, t; }"
        : "=r"(a) : "l"(p));
    return a;
}
__device__ __forceinline__ void ldsm4(uint32_t* r, uint32_t addr) {
    asm volatile("ldmatrix.sync.aligned.m8n8.x4.shared.b16 {%0,%1,%2,%3}, [%4];"
                 : "=r"(r[0]), "=r"(r[1]), "=r"(r[2]), "=r"(r[3]) : "r"(addr));
}
__device__ __forceinline__ void mma16816(float* d, const uint32_t* a,
                                         uint32_t b0, uint32_t b1) {
    asm volatile(
        "mma.sync.aligned.m16n8k16.row.col.f32.bf16.bf16.f32 "
        "{%0,%1,%2,%3}, {%4,%5,%6,%7}, {%8,%9}, {%0,%1,%2,%3};"
        : "+f"(d[0]), "+f"(d[1]), "+f"(d[2]), "+f"(d[3])
        : "r"(a[0]), "r"(a[1]), "r"(a[2]), "r"(a[3]), "r"(b0), "r"(b1));
}
// FMA-pipe exp2: round + degree-6 poly on [-0.5,0.5], exponent splice.
// Max rel err ~1e-7. Avoids MUFU (rt=8/SMSP was the softmax bottleneck).
__device__ __forceinline__ float exp2_fast(float x) {
    x = fmaxf(x, -100.f);
    float fi;
    asm("cvt.rni.f32.f32 %0, %1;" : "=f"(fi) : "f"(x));
    float f = x - fi;
    float p = 1.53533618831950e-4f;
    p = fmaf(p, f, 1.33988744026657e-3f);
    p = fmaf(p, f, 9.61843735767464e-3f);
    p = fmaf(p, f, 5.55033247116281e-2f);
    p = fmaf(p, f, 2.40226479136301e-1f);
    p = fmaf(p, f, 6.93147202855042e-1f);
    p = fmaf(p, f, 1.0f);
    return __int_as_float(__float_as_int(p) + ((int)fi << 23));
}
#define CP_ASYNC16(dst, src) \
    asm volatile("cp.async.cg.shared.global [%0], [%1], 16;" \
                 :: "r"(dst), "l"(src) : "memory")
#define CP_COMMIT()  asm volatile("cp.async.commit_group;" ::: "memory")
#define CP_WAIT0()   asm volatile("cp.async.wait_group 0;" ::: "memory")

__device__ __forceinline__ void split1(float v, __nv_bfloat16& h, __nv_bfloat16& l) {
    h = __float2bfloat16(v);
    l = __float2bfloat16(v - __bfloat162float(h));
}

// ---------------------------------------------------------------------------
// Fused weight split (all 5 weight tensors, grid-stride)
// ---------------------------------------------------------------------------
__global__ void split_weights(const float* __restrict__ qkv_w,
                              const float* __restrict__ fc_w,
                              const float* __restrict__ w1,
                              const float* __restrict__ w2,
                              const float* __restrict__ out_w)
{
    const int c0 = 196608, c1 = c0 + 65536, c2 = c1 + 262144,
              c3 = c2 + 262144, c4 = c3 + 2048000;
    int stride = gridDim.x * blockDim.x;
    for (int idx = blockIdx.x * blockDim.x + threadIdx.x; idx < c4; idx += stride) {
        const float* src; __nv_bfloat16 *dh, *dl; int li;
        if (idx < c0)      { src = qkv_w; dh = g_wqkv_h; dl = g_wqkv_l; li = idx; }
        else if (idx < c1) { src = fc_w;  dh = g_wfc_h;  dl = g_wfc_l;  li = idx - c0; }
        else if (idx < c2) { src = w1;    dh = g_w1_h;   dl = g_w1_l;   li = idx - c1; }
        else if (idx < c3) { src = w2;    dh = g_w2_h;   dl = g_w2_l;   li = idx - c2; }
        else               { src = out_w; dh = g_wout_h; dl = g_wout_l; li = idx - c3; }
        float4 v = ((const float4*)src)[li];
        __nv_bfloat16 h0, h1, h2, h3, l0, l1, l2, l3;
        split1(v.x, h0, l0); split1(v.y, h1, l1);
        split1(v.z, h2, l2); split1(v.w, h3, l3);
        ((__nv_bfloat162*)dh)[li * 2 + 0] = __nv_bfloat162(h0, h1);
        ((__nv_bfloat162*)dh)[li * 2 + 1] = __nv_bfloat162(h2, h3);
        ((__nv_bfloat162*)dl)[li * 2 + 0] = __nv_bfloat162(l0, l1);
        ((__nv_bfloat162*)dl)[li * 2 + 1] = __nv_bfloat162(l2, l3);
    }
}

// ---------------------------------------------------------------------------
// mma.sync bf16x3 GEMM. TM in {128, 64}, TN = 128. (unchanged from R5)
// ---------------------------------------------------------------------------
#define GSMEM128 (2 * 65536)
#define GSMEM64  (2 * 49152)

template<int TM, int N, int K, int RELU, int WSPLIT>
__device__ __forceinline__ void gemm_body(
    const __nv_bfloat16* __restrict__ Ah, const __nv_bfloat16* __restrict__ Al,
    const __nv_bfloat16* __restrict__ Bh, const __nv_bfloat16* __restrict__ Bl,
    const float* __restrict__ bias, float* __restrict__ C,
    __nv_bfloat16* __restrict__ Ch, __nv_bfloat16* __restrict__ Cl)
{
    extern __shared__ char smem[];
    const uint32_t sb = smem_to_u32(smem);
    const int tid  = threadIdx.x;
    const int wid  = tid >> 5;
    const int lane = tid & 31;
    const int m0   = blockIdx.y * TM;
    const int n0   = blockIdx.x << 7;
    constexpr int NST   = K / 64;
    constexpr int STAGE = (TM == 128) ? 65536 : 49152;
    constexpr int AOFF  = (TM == 128) ? 16384 : 8192;
    constexpr int BOFF  = (TM == 128) ? 32768 : 16384;
    constexpr int BSZ   = 16384;
    const int wr = (TM == 128) ? (wid & 3) : (wid & 1);
    const int wc = (TM == 128) ? (wid >> 2) : (wid >> 1);

    float acc[2][4][4];
#pragma unroll
    for (int i = 0; i < 2; i++)
#pragma unroll
        for (int j = 0; j < 4; j++)
#pragma unroll
            for (int q = 0; q < 4; q++) acc[i][j][q] = 0.f;

    const __nv_bfloat16 *gp128 = nullptr;
    uint32_t dst128 = 0, sw128v = 0;
    const __nv_bfloat16 *pah = nullptr, *pal = nullptr, *pbh = nullptr, *pbl = nullptr;
    uint32_t dq = 0, swq = 0;
    if (TM == 128) {
        const int lr = tid & 127;
        const int lt = tid >> 7;
        gp128 = (lt == 0) ? Ah + (long)(m0 + lr) * K :
                (lt == 1) ? Al + (long)(m0 + lr) * K :
                (lt == 2) ? Bh + (long)(n0 + lr) * K :
                            Bl + (long)(n0 + lr) * K;
        dst128 = sb + lt * 16384 + lr * 128;
        sw128v = (uint32_t)((lr & 7) << 4);
    } else {
        const int q = tid >> 3;
        uint32_t cbyte = (uint32_t)((tid & 7) << 4);
        swq   = cbyte ^ (uint32_t)((q & 7) << 4);
        dq    = (uint32_t)q;
        const int ce = (tid & 7) << 3;
        pah = Ah + (long)(m0 + q) * K + ce;
        pal = Al + (long)(m0 + q) * K + ce;
        pbh = Bh + (long)(n0 + q) * K + ce;
        pbl = Bl + (long)(n0 + q) * K + ce;
    }

#define LOAD_STAGE(sbuf, koff)                                                  \
    do {                                                                        \
        if (TM == 128) {                                                        \
            const char* src = (const char*)(gp128 + (koff));                    \
            uint32_t db = dst128 + (sbuf) * (uint32_t)STAGE;                    \
            _Pragma("unroll")                                                   \
            for (int c = 0; c < 8; c++)                                         \
                CP_ASYNC16(db + (uint32_t)((c * 16) ^ sw128v), src + c * 16);   \
        } else {                                                                \
            uint32_t base = sb + (sbuf) * (uint32_t)STAGE;                      \
            _Pragma("unroll")                                                   \
            for (int u = 0; u < 2; u++) {                                       \
                uint32_t row = dq + u * 32;                                     \
                CP_ASYNC16(base + row * 128 + swq,                              \
                           (const char*)(pah + (long)u * 32 * K + (koff)));     \
                CP_ASYNC16(base + AOFF + row * 128 + swq,                       \
                           (const char*)(pal + (long)u * 32 * K + (koff)));     \
            }                                                                   \
            _Pragma("unroll")                                                   \
            for (int u = 0; u < 4; u++) {                                       \
                uint32_t row = dq + u * 32;                                     \
                CP_ASYNC16(base + BOFF + row * 128 + swq,                       \
                           (const char*)(pbh + (long)u * 32 * K + (koff)));     \
                CP_ASYNC16(base + BOFF + BSZ + row * 128 + swq,                 \
                           (const char*)(pbl + (long)u * 32 * K + (koff)));     \
            }                                                                   \
        }                                                                       \
        CP_COMMIT();                                                            \
    } while (0)

    LOAD_STAGE(0, 0);

    for (int s = 0; s < NST; s++) {
        CP_WAIT0();
        __syncthreads();
        if (s + 1 < NST) LOAD_STAGE((s + 1) & 1, (s + 1) * 64);
        const uint32_t bufb = sb + (uint32_t)((s & 1) * STAGE);

#pragma unroll
        for (int ko = 0; ko < 64; ko += 16) {
            uint32_t afr[2][2][4];
            uint32_t bfr[2][2][4];
            {
                const int rowb = wr * 32 + (lane & 15);
                const int cb   = ko * 2 + ((lane >> 4) << 4);
#pragma unroll
                for (int t = 0; t < 2; t++)
#pragma unroll
                    for (int mi = 0; mi < 2; mi++) {
                        int row = rowb + mi * 16;
                        uint32_t addr = bufb + (uint32_t)(t * AOFF) + row * 128
                                      + (uint32_t)(cb ^ ((row & 7) << 4));
                        ldsm4(afr[t][mi], addr);
                    }
            }
            {
                const int rowb = wc * 32 + (lane & 7) + ((lane >> 4) << 3);
                const int cb   = ko * 2 + (((lane >> 3) & 1) << 4);
#pragma unroll
                for (int t = 0; t < 2; t++)
#pragma unroll
                    for (int nj = 0; nj < 2; nj++) {
                        int row = rowb + nj * 16;
                        uint32_t addr = bufb + (uint32_t)BOFF + (uint32_t)(t * BSZ)
                                      + row * 128 + (uint32_t)(cb ^ ((row & 7) << 4));
                        ldsm4(bfr[t][nj], addr);
                    }
            }
#pragma unroll
            for (int mi = 0; mi < 2; mi++)
#pragma unroll
                for (int nj = 0; nj < 2; nj++)
#pragma unroll
                    for (int hh = 0; hh < 2; hh++) {
                        const int nc = nj * 2 + hh;
                        const uint32_t bh0 = bfr[0][nj][hh * 2];
                        const uint32_t bh1 = bfr[0][nj][hh * 2 + 1];
                        const uint32_t bl0 = bfr[1][nj][hh * 2];
                        const uint32_t bl1 = bfr[1][nj][hh * 2 + 1];
                        mma16816(acc[mi][nc], afr[0][mi], bh0, bh1);
                        mma16816(acc[mi][nc], afr[0][mi], bl0, bl1);
                        mma16816(acc[mi][nc], afr[1][mi], bh0, bh1);
                    }
        }
        __syncthreads();
    }
#undef LOAD_STAGE

#pragma unroll
    for (int mi = 0; mi < 2; mi++)
#pragma unroll
        for (int nc = 0; nc < 4; nc++) {
            int row = m0 + wr * 32 + mi * 16 + (lane >> 2);
            int col = n0 + wc * 32 + nc * 8 + (lane & 3) * 2;
            float b0v = bias[col], b1v = bias[col + 1];
            float v0 = acc[mi][nc][0] + b0v;
            float v1 = acc[mi][nc][1] + b1v;
            float v2 = acc[mi][nc][2] + b0v;
            float v3 = acc[mi][nc][3] + b1v;
            if (RELU) {
                v0 = fmaxf(v0, 0.f); v1 = fmaxf(v1, 0.f);
                v2 = fmaxf(v2, 0.f); v3 = fmaxf(v3, 0.f);
            }
            if (WSPLIT) {
                __nv_bfloat16 h0, h1, h2, h3, l0, l1, l2, l3;
                split1(v0, h0, l0); split1(v1, h1, l1);
                split1(v2, h2, l2); split1(v3, h3, l3);
                *(__nv_bfloat162*)(Ch + (long)row * N + col)       = __nv_bfloat162(h0, h1);
                *(__nv_bfloat162*)(Ch + (long)(row + 8) * N + col) = __nv_bfloat162(h2, h3);
                *(__nv_bfloat162*)(Cl + (long)row * N + col)       = __nv_bfloat162(l0, l1);
                *(__nv_bfloat162*)(Cl + (long)(row + 8) * N + col) = __nv_bfloat162(l2, l3);
            } else {
                *(float2*)(C + (long)row * N + col)       = make_float2(v0, v1);
                *(float2*)(C + (long)(row + 8) * N + col) = make_float2(v2, v3);
            }
        }
}

__global__ __launch_bounds__(256) void gemm_qkv_tc(int l, const float* bias)
{ gemm_body<64, 768, 256, 0, 0>(g_acth, g_actl, g_wqkv_h + l*196608, g_wqkv_l + l*196608,
                                bias, g_qkv, nullptr, nullptr); }
__global__ __launch_bounds__(256) void gemm_fc_tc(int l, const float* bias)
{ gemm_body<64, 256, 256, 0, 0>(g_acth, g_actl, g_wfc_h + l*65536, g_wfc_l + l*65536,
                                bias, g_tmp, nullptr, nullptr); }
__global__ __launch_bounds__(512) void gemm_w1_tc(int l, const float* bias)
{ gemm_body<128, 1024, 256, 1, 1>(g_acth, g_actl, g_w1_h + l*262144, g_w1_l + l*262144,
                                  bias, nullptr, g_hh, g_hl); }
__global__ __launch_bounds__(256) void gemm_w2_tc(int l, const float* bias)
{ gemm_body<64, 256, 1024, 0, 0>(g_hh, g_hl, g_w2_h + l*262144, g_w2_l + l*262144,
                                 bias, g_tmp, nullptr, nullptr); }
__global__ __launch_bounds__(512) void gemm_logits_tc(const float* bias, float* out)
{ gemm_body<128, 32000, 256, 0, 0>(g_acth, g_actl, g_wout_h, g_wout_l,
                                   bias, out, nullptr, nullptr); }

// ---------------------------------------------------------------------------
// Embedding + positional encoding (writes x and hi/lo)
// ---------------------------------------------------------------------------
__global__ void embed_pos_kernel(const int* __restrict__ tok,
                                 const float* __restrict__ emb)
{
    int row = blockIdx.x;
    int d   = threadIdx.x;
    int t   = row & (Tn - 1);
    int token = tok[row];
    double div = exp(-(double)(d & ~1) * (9.210340371976184 / 256.0));
    double ang = (double)t * div;
    float  pe  = (d & 1) ? (float)cos(ang) : (float)sin(ang);
    float v = emb[token * Dn + d] + pe;
    g_x[row * Dn + d] = v;
    __nv_bfloat16 h, l;
    split1(v, h, l);
    g_acth[row * Dn + d] = h;
    g_actl[row * Dn + d] = l;
}

// ---------------------------------------------------------------------------
// Flash attention (causal), fp32. One 64-row q-tile per block, grid (32, 8)
// = 256 blocks (> 148 SMs; triangular load balanced by work-stealing).
// log2-domain softmax with FMA-pipe exp2_fast. Output -> bf16 hi/lo.
// ---------------------------------------------------------------------------
#define SWZ(r, c) ((c) ^ (((r) & 15) << 2))
#define QSCALE 0.18033688f    /* 0.125 * log2(e) */

__global__ __launch_bounds__(256) void attn_kernel()
{
    __shared__ float Qs[4096];
    __shared__ float KPs[4096];
    __shared__ float Vs[4096];

    const int tid = threadIdx.x;
    const int tx  = tid & 15;
    const int ty  = tid >> 4;
    const int qt  = blockIdx.x;
    const int b   = blockIdx.y >> 2;
    const int h   = blockIdx.y & 3;
    const int q0  = qt << 6;
    const float* qbase = g_qkv + (long)b * Tn * 768 + h * 64;

#pragma unroll
    for (int rep = 0; rep < 4; rep++) {
        int idx = tid + rep * 256;
        int rr  = idx >> 4;
        int d4  = (idx & 15) << 2;
        float4 q4 = *(const float4*)(qbase + (long)(q0 + rr) * 768 + d4);
        Qs[(d4 + 0) * 64 + SWZ(d4 + 0, rr)] = q4.x * QSCALE;
        Qs[(d4 + 1) * 64 + SWZ(d4 + 1, rr)] = q4.y * QSCALE;
        Qs[(d4 + 2) * 64 + SWZ(d4 + 2, rr)] = q4.z * QSCALE;
        Qs[(d4 + 3) * 64 + SWZ(d4 + 3, rr)] = q4.w * QSCALE;
    }

    float m_i[4], l_i[4], o[4][4];
#pragma unroll
    for (int i = 0; i < 4; i++) {
        m_i[i] = -1e30f; l_i[i] = 0.f;
#pragma unroll
        for (int j = 0; j < 4; j++) o[i][j] = 0.f;
    }

    for (int kt = 0; kt <= qt; kt++) {
        __syncthreads();
        const int k0 = kt << 6;
#pragma unroll
        for (int rep = 0; rep < 4; rep++) {
            int idx = tid + rep * 256;
            int rr  = idx >> 4;
            int d4  = (idx & 15) << 2;
            const float* kb = qbase + (long)(k0 + rr) * 768;
            float4 k4 = *(const float4*)(kb + 256 + d4);
            KPs[(d4 + 0) * 64 + SWZ(d4 + 0, rr)] = k4.x;
            KPs[(d4 + 1) * 64 + SWZ(d4 + 1, rr)] = k4.y;
            KPs[(d4 + 2) * 64 + SWZ(d4 + 2, rr)] = k4.z;
            KPs[(d4 + 3) * 64 + SWZ(d4 + 3, rr)] = k4.w;
            float4 v4 = *(const float4*)(kb + 512 + d4);
            *(float4*)(Vs + rr * 64 + d4) = v4;
        }
        __syncthreads();

        float s[4][4];
#pragma unroll
        for (int i = 0; i < 4; i++)
#pragma unroll
            for (int j = 0; j < 4; j++) s[i][j] = 0.f;
#pragma unroll 8
        for (int d = 0; d < 64; d++) {
            float4 qa = *(const float4*)&Qs[d * 64 + SWZ(d, ty * 4)];
            float4 ka = *(const float4*)&KPs[d * 64 + SWZ(d, tx * 4)];
            float qv[4] = {qa.x, qa.y, qa.z, qa.w};
            float kv[4] = {ka.x, ka.y, ka.z, ka.w};
#pragma unroll
            for (int i = 0; i < 4; i++)
#pragma unroll
                for (int j = 0; j < 4; j++)
                    s[i][j] = fmaf(qv[i], kv[j], s[i][j]);
        }

        if (kt == qt) {
#pragma unroll
            for (int i = 0; i < 4; i++)
#pragma unroll
                for (int j = 0; j < 4; j++)
                    if (tx * 4 + j > ty * 4 + i) s[i][j] = -1e30f;
        }

#pragma unroll
        for (int i = 0; i < 4; i++) {
            float mx = fmaxf(fmaxf(s[i][0], s[i][1]), fmaxf(s[i][2], s[i][3]));
#pragma unroll
            for (int ofs = 8; ofs; ofs >>= 1)
                mx = fmaxf(mx, __shfl_xor_sync(0xffffffffu, mx, ofs, 16));
            float mn   = fmaxf(m_i[i], mx);
            float corr = exp2_fast(m_i[i] - mn);
            float rs = 0.f;
#pragma unroll
            for (int j = 0; j < 4; j++) {
                s[i][j] = exp2_fast(s[i][j] - mn);
                rs += s[i][j];
            }
#pragma unroll
            for (int ofs = 8; ofs; ofs >>= 1)
                rs += __shfl_xor_sync(0xffffffffu, rs, ofs, 16);
            l_i[i] = l_i[i] * corr + rs;
            m_i[i] = mn;
#pragma unroll
            for (int j = 0; j < 4; j++) o[i][j] *= corr;
        }

        __syncthreads();
#pragma unroll
        for (int i = 0; i < 4; i++)
#pragma unroll
            for (int j = 0; j < 4; j++) {
                int n = tx * 4 + j;
                KPs[n * 64 + SWZ(n, ty * 4 + i)] = s[i][j];
            }
        __syncthreads();

#pragma unroll 8
        for (int n = 0; n < 64; n++) {
            float4 p4 = *(const float4*)&KPs[n * 64 + SWZ(n, ty * 4)];
            float4 v4 = *(const float4*)&Vs[n * 64 + tx * 4];
            float pv[4] = {p4.x, p4.y, p4.z, p4.w};
            float vv[4] = {v4.x, v4.y, v4.z, v4.w};
#pragma unroll
            for (int i = 0; i < 4; i++)
#pragma unroll
                for (int j = 0; j < 4; j++)
                    o[i][j] = fmaf(pv[i], vv[j], o[i][j]);
        }
    }

    // write O as bf16 hi/lo (A operand of fc GEMM)
#pragma unroll
    for (int i = 0; i < 4; i++) {
        float inv = 1.f / l_i[i];
        long base = (long)(b * Tn + q0 + ty * 4 + i) * Dn + h * 64 + tx * 4;
        __nv_bfloat16 h0, h1, h2, h3, l0, l1, l2, l3;
        split1(o[i][0] * inv, h0, l0); split1(o[i][1] * inv, h1, l1);
        split1(o[i][2] * inv, h2, l2); split1(o[i][3] * inv, h3, l3);
        *(__nv_bfloat162*)(g_acth + base)     = __nv_bfloat162(h0, h1);
        *(__nv_bfloat162*)(g_acth + base + 2) = __nv_bfloat162(h2, h3);
        *(__nv_bfloat162*)(g_actl + base)     = __nv_bfloat162(l0, l1);
        *(__nv_bfloat162*)(g_actl + base + 2) = __nv_bfloat162(l2, l3);
    }
}

// ---------------------------------------------------------------------------
// LayerNorm: x = LN(x [+ g_tmp]) * sc + bi ; writes x fp32 AND hi/lo bf16.
// ---------------------------------------------------------------------------
template<int ADD>
__device__ __forceinline__ void ln_body(const float* __restrict__ sc,
                                        const float* __restrict__ bi)
{
    int row  = blockIdx.x * 8 + (threadIdx.x >> 5);
    int lane = threadIdx.x & 31;
    const float* pa = g_x + (long)row * Dn + lane * 8;
    float v[8];
    {
        float4 v0 = *(const float4*)pa;
        float4 v1 = *(const float4*)(pa + 4);
        v[0] = v0.x; v[1] = v0.y; v[2] = v0.z; v[3] = v0.w;
        v[4] = v1.x; v[5] = v1.y; v[6] = v1.z; v[7] = v1.w;
    }
    if (ADD) {
        const float* pr = g_tmp + (long)row * Dn + lane * 8;
        float4 r0 = *(const float4*)pr;
        float4 r1 = *(const float4*)(pr + 4);
        v[0] += r0.x; v[1] += r0.y; v[2] += r0.z; v[3] += r0.w;
        v[4] += r1.x; v[5] += r1.y; v[6] += r1.z; v[7] += r1.w;
    }
    float s = 0.f;
#pragma unroll
    for (int k = 0; k < 8; k++) s += v[k];
#pragma unroll
    for (int ofs = 16; ofs; ofs >>= 1) s += __shfl_xor_sync(0xffffffffu, s, ofs);
    float mu = s * (1.f / 256.f);
    float var = 0.f;
#pragma unroll
    for (int k = 0; k < 8; k++) { float d = v[k] - mu; var = fmaf(d, d, var); }
#pragma unroll
    for (int ofs = 16; ofs; ofs >>= 1) var += __shfl_xor_sync(0xffffffffu, var, ofs);
    float rstd = rsqrtf(var * (1.f / 256.f) + 1e-5f);

    float4 s0 = *(const float4*)(sc + lane * 8);
    float4 s1 = *(const float4*)(sc + lane * 8 + 4);
    float4 b0 = *(const float4*)(bi + lane * 8);
    float4 b1 = *(const float4*)(bi + lane * 8 + 4);
    float scv[8] = {s0.x, s0.y, s0.z, s0.w, s1.x, s1.y, s1.z, s1.w};
    float biv[8] = {b0.x, b0.y, b0.z, b0.w, b1.x, b1.y, b1.z, b1.w};
    float o[8];
    __nv_bfloat16 oh[8], ol[8];
#pragma unroll
    for (int k = 0; k < 8; k++) {
        o[k] = fmaf((v[k] - mu) * rstd, scv[k], biv[k]);
        split1(o[k], oh[k], ol[k]);
    }
    long base = (long)row * Dn + lane * 8;
    *(float4*)(g_x + base)     = make_float4(o[0], o[1], o[2], o[3]);
    *(float4*)(g_x + base + 4) = make_float4(o[4], o[5], o[6], o[7]);
#pragma unroll
    for (int k = 0; k < 4; k++) {
        ((__nv_bfloat162*)(g_acth + base))[k] = __nv_bfloat162(oh[2*k], oh[2*k+1]);
        ((__nv_bfloat162*)(g_actl + base))[k] = __nv_bfloat162(ol[2*k], ol[2*k+1]);
    }
}
__global__ void add_ln_kernel(const float* sc, const float* bi) { ln_body<1>(sc, bi); }
__global__ void final_ln_kernel(const float* sc, const float* bi) { ln_body<0>(sc, bi); }

// ---------------------------------------------------------------------------
// Orchestration
// ---------------------------------------------------------------------------
extern "C" void kernel_launch(void* const* d_in, const int* in_sizes, int n_in,
                              void* d_out, int out_size)
{
    const int*   tokens = (const int*)d_in[0];
    const float* embedw = (const float*)d_in[1];
    const float* qkv_w  = (const float*)d_in[2];
    const float* qkv_b  = (const float*)d_in[3];
    const float* fc_w   = (const float*)d_in[4];
    const float* fc_b   = (const float*)d_in[5];
    const float* w1     = (const float*)d_in[8];
    const float* b1     = (const float*)d_in[9];
    const float* w2     = (const float*)d_in[10];
    const float* b2     = (const float*)d_in[11];
    const float* ln1_s  = (const float*)d_in[6];
    const float* ln1_b  = (const float*)d_in[7];
    const float* ln2_s  = (const float*)d_in[12];
    const float* ln2_b  = (const float*)d_in[13];
    const float* lnf_s  = (const float*)d_in[14];
    const float* lnf_b  = (const float*)d_in[15];
    const float* out_w  = (const float*)d_in[16];
    const float* out_b  = (const float*)d_in[17];
    float* logits = (float*)d_out;

    cudaFuncSetAttribute((const void*)gemm_qkv_tc,
        cudaFuncAttributeMaxDynamicSharedMemorySize, GSMEM64);
    cudaFuncSetAttribute((const void*)gemm_fc_tc,
        cudaFuncAttributeMaxDynamicSharedMemorySize, GSMEM64);
    cudaFuncSetAttribute((const void*)gemm_w1_tc,
        cudaFuncAttributeMaxDynamicSharedMemorySize, GSMEM128);
    cudaFuncSetAttribute((const void*)gemm_w2_tc,
        cudaFuncAttributeMaxDynamicSharedMemorySize, GSMEM64);
    cudaFuncSetAttribute((const void*)gemm_logits_tc,
        cudaFuncAttributeMaxDynamicSharedMemorySize, GSMEM128);

    split_weights<<<2048, 256>>>(qkv_w, fc_w, w1, w2, out_w);
    embed_pos_kernel<<<Mrows, Dn>>>(tokens, embedw);

    for (int l = 0; l < 4; l++) {
        gemm_qkv_tc<<<dim3(6, 64), 256, GSMEM64>>>(l, qkv_b + l * 768);
        attn_kernel<<<dim3(32, Bn * 4), 256>>>();
        gemm_fc_tc<<<dim3(2, 64), 256, GSMEM64>>>(l, fc_b + l * 256);
        add_ln_kernel<<<Mrows / 8, 256>>>(ln1_s + l * 256, ln1_b + l * 256);
        gemm_w1_tc<<<dim3(8, 32), 512, GSMEM128>>>(l, b1 + l * 1024);
        gemm_w2_tc<<<dim3(2, 64), 256, GSMEM64>>>(l, b2 + l * 256);
        add_ln_kernel<<<Mrows / 8, 256>>>(ln2_s + l * 256, ln2_b + l * 256);
    }
    final_ln_kernel<<<Mrows / 8, 256>>>(lnf_s, lnf_b);
    gemm_logits_tc<<<dim3(250, 32), 512, GSMEM128>>>(out_b, logits);
}

// round 7
// speedup vs baseline: 1.4458x; 1.4458x over previous
#include <cuda_runtime.h>
#include <cuda_bf16.h>
#include <math.h>
#include <stdint.h>

// ---------------------------------------------------------------------------
// MiniGPT forward. B=2 T=2048 D=256 H=4 DK=64 DFF=1024 L=4 V=32000
// GEMMs: mma.sync bf16x3 compensated split (R5, unchanged).
// Attention: NEW — HMMA flash kernel (bf16x3 S and PV), warp-local softmax.
// ---------------------------------------------------------------------------

#define Tn    2048
#define Bn    2
#define Dn    256
#define Mrows 4096

// fp32 scratch
__device__ float g_x[Mrows * Dn];
__device__ float g_qkv[Mrows * 3 * Dn];
__device__ float g_tmp[Mrows * Dn];

// bf16 hi/lo activations (D-wide) and MLP hidden (DFF-wide)
__device__ __nv_bfloat16 g_acth[Mrows * Dn],  g_actl[Mrows * Dn];
__device__ __nv_bfloat16 g_hh[Mrows * 1024],  g_hl[Mrows * 1024];

// bf16 hi/lo weights
__device__ __nv_bfloat16 g_wqkv_h[4 * 768 * 256],  g_wqkv_l[4 * 768 * 256];
__device__ __nv_bfloat16 g_wfc_h [4 * 256 * 256],  g_wfc_l [4 * 256 * 256];
__device__ __nv_bfloat16 g_w1_h  [4 * 1024 * 256], g_w1_l  [4 * 1024 * 256];
__device__ __nv_bfloat16 g_w2_h  [4 * 256 * 1024], g_w2_l  [4 * 256 * 1024];
__device__ __nv_bfloat16 g_wout_h[32000 * 256],    g_wout_l[32000 * 256];

// ---------------------------------------------------------------------------
// PTX helpers
// ---------------------------------------------------------------------------
__device__ __forceinline__ uint32_t smem_to_u32(const void* p) {
    uint32_t a;
    asm("{ .reg .u64 t; cvta.to.shared.u64 t, %1; cvt.u32.u64 %0, t; }"
        : "=r"(a) : "l"(p));
    return a;
}
__device__ __forceinline__ void ldsm4(uint32_t* r, uint32_t addr) {
    asm volatile("ldmatrix.sync.aligned.m8n8.x4.shared.b16 {%0,%1,%2,%3}, [%4];"
                 : "=r"(r[0]), "=r"(r[1]), "=r"(r[2]), "=r"(r[3]) : "r"(addr));
}
__device__ __forceinline__ void mma16816(float* d, const uint32_t* a,
                                         uint32_t b0, uint32_t b1) {
    asm volatile(
        "mma.sync.aligned.m16n8k16.row.col.f32.bf16.bf16.f32 "
        "{%0,%1,%2,%3}, {%4,%5,%6,%7}, {%8,%9}, {%0,%1,%2,%3};"
        : "+f"(d[0]), "+f"(d[1]), "+f"(d[2]), "+f"(d[3])
        : "r"(a[0]), "r"(a[1]), "r"(a[2]), "r"(a[3]), "r"(b0), "r"(b1));
}
__device__ __forceinline__ float ex2f(float x) {
    float y;
    asm("ex2.approx.f32 %0, %1;" : "=f"(y) : "f"(x));
    return y;
}
#define CP_ASYNC16(dst, src) \
    asm volatile("cp.async.cg.shared.global [%0], [%1], 16;" \
                 :: "r"(dst), "l"(src) : "memory")
#define CP_COMMIT()  asm volatile("cp.async.commit_group;" ::: "memory")
#define CP_WAIT0()   asm volatile("cp.async.wait_group 0;" ::: "memory")

__device__ __forceinline__ void split1(float v, __nv_bfloat16& h, __nv_bfloat16& l) {
    h = __float2bfloat16(v);
    l = __float2bfloat16(v - __bfloat162float(h));
}
__device__ __forceinline__ uint32_t pack2(__nv_bfloat16 a, __nv_bfloat16 b) {
    __nv_bfloat162 t(a, b);
    return *(uint32_t*)&t;
}

// ---------------------------------------------------------------------------
// Fused weight split (all 5 weight tensors, grid-stride)
// ---------------------------------------------------------------------------
__global__ void split_weights(const float* __restrict__ qkv_w,
                              const float* __restrict__ fc_w,
                              const float* __restrict__ w1,
                              const float* __restrict__ w2,
                              const float* __restrict__ out_w)
{
    const int c0 = 196608, c1 = c0 + 65536, c2 = c1 + 262144,
              c3 = c2 + 262144, c4 = c3 + 2048000;
    int stride = gridDim.x * blockDim.x;
    for (int idx = blockIdx.x * blockDim.x + threadIdx.x; idx < c4; idx += stride) {
        const float* src; __nv_bfloat16 *dh, *dl; int li;
        if (idx < c0)      { src = qkv_w; dh = g_wqkv_h; dl = g_wqkv_l; li = idx; }
        else if (idx < c1) { src = fc_w;  dh = g_wfc_h;  dl = g_wfc_l;  li = idx - c0; }
        else if (idx < c2) { src = w1;    dh = g_w1_h;   dl = g_w1_l;   li = idx - c1; }
        else if (idx < c3) { src = w2;    dh = g_w2_h;   dl = g_w2_l;   li = idx - c2; }
        else               { src = out_w; dh = g_wout_h; dl = g_wout_l; li = idx - c3; }
        float4 v = ((const float4*)src)[li];
        __nv_bfloat16 h0, h1, h2, h3, l0, l1, l2, l3;
        split1(v.x, h0, l0); split1(v.y, h1, l1);
        split1(v.z, h2, l2); split1(v.w, h3, l3);
        ((__nv_bfloat162*)dh)[li * 2 + 0] = __nv_bfloat162(h0, h1);
        ((__nv_bfloat162*)dh)[li * 2 + 1] = __nv_bfloat162(h2, h3);
        ((__nv_bfloat162*)dl)[li * 2 + 0] = __nv_bfloat162(l0, l1);
        ((__nv_bfloat162*)dl)[li * 2 + 1] = __nv_bfloat162(l2, l3);
    }
}

// ---------------------------------------------------------------------------
// mma.sync bf16x3 GEMM (R5, unchanged)
// ---------------------------------------------------------------------------
#define GSMEM128 (2 * 65536)
#define GSMEM64  (2 * 49152)

template<int TM, int N, int K, int RELU, int WSPLIT>
__device__ __forceinline__ void gemm_body(
    const __nv_bfloat16* __restrict__ Ah, const __nv_bfloat16* __restrict__ Al,
    const __nv_bfloat16* __restrict__ Bh, const __nv_bfloat16* __restrict__ Bl,
    const float* __restrict__ bias, float* __restrict__ C,
    __nv_bfloat16* __restrict__ Ch, __nv_bfloat16* __restrict__ Cl)
{
    extern __shared__ char smem[];
    const uint32_t sb = smem_to_u32(smem);
    const int tid  = threadIdx.x;
    const int wid  = tid >> 5;
    const int lane = tid & 31;
    const int m0   = blockIdx.y * TM;
    const int n0   = blockIdx.x << 7;
    constexpr int NST   = K / 64;
    constexpr int STAGE = (TM == 128) ? 65536 : 49152;
    constexpr int AOFF  = (TM == 128) ? 16384 : 8192;
    constexpr int BOFF  = (TM == 128) ? 32768 : 16384;
    constexpr int BSZ   = 16384;
    const int wr = (TM == 128) ? (wid & 3) : (wid & 1);
    const int wc = (TM == 128) ? (wid >> 2) : (wid >> 1);

    float acc[2][4][4];
#pragma unroll
    for (int i = 0; i < 2; i++)
#pragma unroll
        for (int j = 0; j < 4; j++)
#pragma unroll
            for (int q = 0; q < 4; q++) acc[i][j][q] = 0.f;

    const __nv_bfloat16 *gp128 = nullptr;
    uint32_t dst128 = 0, sw128v = 0;
    const __nv_bfloat16 *pah = nullptr, *pal = nullptr, *pbh = nullptr, *pbl = nullptr;
    uint32_t dq = 0, swq = 0;
    if (TM == 128) {
        const int lr = tid & 127;
        const int lt = tid >> 7;
        gp128 = (lt == 0) ? Ah + (long)(m0 + lr) * K :
                (lt == 1) ? Al + (long)(m0 + lr) * K :
                (lt == 2) ? Bh + (long)(n0 + lr) * K :
                            Bl + (long)(n0 + lr) * K;
        dst128 = sb + lt * 16384 + lr * 128;
        sw128v = (uint32_t)((lr & 7) << 4);
    } else {
        const int q = tid >> 3;
        uint32_t cbyte = (uint32_t)((tid & 7) << 4);
        swq   = cbyte ^ (uint32_t)((q & 7) << 4);
        dq    = (uint32_t)q;
        const int ce = (tid & 7) << 3;
        pah = Ah + (long)(m0 + q) * K + ce;
        pal = Al + (long)(m0 + q) * K + ce;
        pbh = Bh + (long)(n0 + q) * K + ce;
        pbl = Bl + (long)(n0 + q) * K + ce;
    }

#define LOAD_STAGE(sbuf, koff)                                                  \
    do {                                                                        \
        if (TM == 128) {                                                        \
            const char* src = (const char*)(gp128 + (koff));                    \
            uint32_t db = dst128 + (sbuf) * (uint32_t)STAGE;                    \
            _Pragma("unroll")                                                   \
            for (int c = 0; c < 8; c++)                                         \
                CP_ASYNC16(db + (uint32_t)((c * 16) ^ sw128v), src + c * 16);   \
        } else {                                                                \
            uint32_t base = sb + (sbuf) * (uint32_t)STAGE;                      \
            _Pragma("unroll")                                                   \
            for (int u = 0; u < 2; u++) {                                       \
                uint32_t row = dq + u * 32;                                     \
                CP_ASYNC16(base + row * 128 + swq,                              \
                           (const char*)(pah + (long)u * 32 * K + (koff)));     \
                CP_ASYNC16(base + AOFF + row * 128 + swq,                       \
                           (const char*)(pal + (long)u * 32 * K + (koff)));     \
            }                                                                   \
            _Pragma("unroll")                                                   \
            for (int u = 0; u < 4; u++) {                                       \
                uint32_t row = dq + u * 32;                                     \
                CP_ASYNC16(base + BOFF + row * 128 + swq,                       \
                           (const char*)(pbh + (long)u * 32 * K + (koff)));     \
                CP_ASYNC16(base + BOFF + BSZ + row * 128 + swq,                 \
                           (const char*)(pbl + (long)u * 32 * K + (koff)));     \
            }                                                                   \
        }                                                                       \
        CP_COMMIT();                                                            \
    } while (0)

    LOAD_STAGE(0, 0);

    for (int s = 0; s < NST; s++) {
        CP_WAIT0();
        __syncthreads();
        if (s + 1 < NST) LOAD_STAGE((s + 1) & 1, (s + 1) * 64);
        const uint32_t bufb = sb + (uint32_t)((s & 1) * STAGE);

#pragma unroll
        for (int ko = 0; ko < 64; ko += 16) {
            uint32_t afr[2][2][4];
            uint32_t bfr[2][2][4];
            {
                const int rowb = wr * 32 + (lane & 15);
                const int cb   = ko * 2 + ((lane >> 4) << 4);
#pragma unroll
                for (int t = 0; t < 2; t++)
#pragma unroll
                    for (int mi = 0; mi < 2; mi++) {
                        int row = rowb + mi * 16;
                        uint32_t addr = bufb + (uint32_t)(t * AOFF) + row * 128
                                      + (uint32_t)(cb ^ ((row & 7) << 4));
                        ldsm4(afr[t][mi], addr);
                    }
            }
            {
                const int rowb = wc * 32 + (lane & 7) + ((lane >> 4) << 3);
                const int cb   = ko * 2 + (((lane >> 3) & 1) << 4);
#pragma unroll
                for (int t = 0; t < 2; t++)
#pragma unroll
                    for (int nj = 0; nj < 2; nj++) {
                        int row = rowb + nj * 16;
                        uint32_t addr = bufb + (uint32_t)BOFF + (uint32_t)(t * BSZ)
                                      + row * 128 + (uint32_t)(cb ^ ((row & 7) << 4));
                        ldsm4(bfr[t][nj], addr);
                    }
            }
#pragma unroll
            for (int mi = 0; mi < 2; mi++)
#pragma unroll
                for (int nj = 0; nj < 2; nj++)
#pragma unroll
                    for (int hh = 0; hh < 2; hh++) {
                        const int nc = nj * 2 + hh;
                        const uint32_t bh0 = bfr[0][nj][hh * 2];
                        const uint32_t bh1 = bfr[0][nj][hh * 2 + 1];
                        const uint32_t bl0 = bfr[1][nj][hh * 2];
                        const uint32_t bl1 = bfr[1][nj][hh * 2 + 1];
                        mma16816(acc[mi][nc], afr[0][mi], bh0, bh1);
                        mma16816(acc[mi][nc], afr[0][mi], bl0, bl1);
                        mma16816(acc[mi][nc], afr[1][mi], bh0, bh1);
                    }
        }
        __syncthreads();
    }
#undef LOAD_STAGE

#pragma unroll
    for (int mi = 0; mi < 2; mi++)
#pragma unroll
        for (int nc = 0; nc < 4; nc++) {
            int row = m0 + wr * 32 + mi * 16 + (lane >> 2);
            int col = n0 + wc * 32 + nc * 8 + (lane & 3) * 2;
            float b0v = bias[col], b1v = bias[col + 1];
            float v0 = acc[mi][nc][0] + b0v;
            float v1 = acc[mi][nc][1] + b1v;
            float v2 = acc[mi][nc][2] + b0v;
            float v3 = acc[mi][nc][3] + b1v;
            if (RELU) {
                v0 = fmaxf(v0, 0.f); v1 = fmaxf(v1, 0.f);
                v2 = fmaxf(v2, 0.f); v3 = fmaxf(v3, 0.f);
            }
            if (WSPLIT) {
                __nv_bfloat16 h0, h1, h2, h3, l0, l1, l2, l3;
                split1(v0, h0, l0); split1(v1, h1, l1);
                split1(v2, h2, l2); split1(v3, h3, l3);
                *(__nv_bfloat162*)(Ch + (long)row * N + col)       = __nv_bfloat162(h0, h1);
                *(__nv_bfloat162*)(Ch + (long)(row + 8) * N + col) = __nv_bfloat162(h2, h3);
                *(__nv_bfloat162*)(Cl + (long)row * N + col)       = __nv_bfloat162(l0, l1);
                *(__nv_bfloat162*)(Cl + (long)(row + 8) * N + col) = __nv_bfloat162(l2, l3);
            } else {
                *(float2*)(C + (long)row * N + col)       = make_float2(v0, v1);
                *(float2*)(C + (long)(row + 8) * N + col) = make_float2(v2, v3);
            }
        }
}

__global__ __launch_bounds__(256) void gemm_qkv_tc(int l, const float* bias)
{ gemm_body<64, 768, 256, 0, 0>(g_acth, g_actl, g_wqkv_h + l*196608, g_wqkv_l + l*196608,
                                bias, g_qkv, nullptr, nullptr); }
__global__ __launch_bounds__(256) void gemm_fc_tc(int l, const float* bias)
{ gemm_body<64, 256, 256, 0, 0>(g_acth, g_actl, g_wfc_h + l*65536, g_wfc_l + l*65536,
                                bias, g_tmp, nullptr, nullptr); }
__global__ __launch_bounds__(512) void gemm_w1_tc(int l, const float* bias)
{ gemm_body<128, 1024, 256, 1, 1>(g_acth, g_actl, g_w1_h + l*262144, g_w1_l + l*262144,
                                  bias, nullptr, g_hh, g_hl); }
__global__ __launch_bounds__(256) void gemm_w2_tc(int l, const float* bias)
{ gemm_body<64, 256, 1024, 0, 0>(g_hh, g_hl, g_w2_h + l*262144, g_w2_l + l*262144,
                                 bias, g_tmp, nullptr, nullptr); }
__global__ __launch_bounds__(512) void gemm_logits_tc(const float* bias, float* out)
{ gemm_body<128, 32000, 256, 0, 0>(g_acth, g_actl, g_wout_h, g_wout_l,
                                   bias, out, nullptr, nullptr); }

// ---------------------------------------------------------------------------
// Embedding + positional encoding
// ---------------------------------------------------------------------------
__global__ void embed_pos_kernel(const int* __restrict__ tok,
                                 const float* __restrict__ emb)
{
    int row = blockIdx.x;
    int d   = threadIdx.x;
    int t   = row & (Tn - 1);
    int token = tok[row];
    double div = exp(-(double)(d & ~1) * (9.210340371976184 / 256.0));
    double ang = (double)t * div;
    float  pe  = (d & 1) ? (float)cos(ang) : (float)sin(ang);
    float v = emb[token * Dn + d] + pe;
    g_x[row * Dn + d] = v;
    __nv_bfloat16 h, l;
    split1(v, h, l);
    g_acth[row * Dn + d] = h;
    g_actl[row * Dn + d] = l;
}

// ---------------------------------------------------------------------------
// HMMA flash attention (causal). Block = 128 thr / 4 warps; q-tile 64
// (warp w owns q-rows [w*16, w*16+16) -> softmax warp-local). K staged 64.
// bf16x3 for S = QK^T and O = PV. V stored transposed [dk][key].
// smem (64KB dyn): Qh 0 | Ql 8K | Kh 16K | Kl 24K | Vh 32K | Vl 40K |
//                  Ph 48K... (offsets below). All tiles 64x64 bf16, 128B rows,
//                  swizzle ^((row&7)<<4) — identical geometry to gemm_body.
// ---------------------------------------------------------------------------
#define AT_QH 0
#define AT_QL 8192
#define AT_KH 16384
#define AT_KL 24576
#define AT_VH 32768
#define AT_VL 40960
#define AT_PH 49152
#define AT_PL 57344
#define ASMEM 65536
#define QSCALE 0.18033688f    /* 0.125 * log2(e) */

__global__ __launch_bounds__(128) void attn_kernel()
{
    extern __shared__ char smem[];
    const uint32_t sb = smem_to_u32(smem);
    const int tid  = threadIdx.x;
    const int lane = tid & 31;
    const int w    = tid >> 5;
    const int qt   = blockIdx.x;
    const int b    = blockIdx.y >> 2;
    const int h    = blockIdx.y & 3;
    const int q0   = qt << 6;
    const float* base = g_qkv + (long)b * Tn * 768 + h * 64;

    const int lrow  = tid & 63;     // loader row
    const int lhalf = tid >> 6;     // loader f4-half

    // ---- load Q (scaled, split h/l, row-major [q][dk]) ---------------------
    {
        const float* qr = base + (long)(q0 + lrow) * 768;
#pragma unroll
        for (int c = 0; c < 8; c++) {
            int f4 = lhalf * 8 + c;
            float4 v = *(const float4*)(qr + f4 * 4);
            v.x *= QSCALE; v.y *= QSCALE; v.z *= QSCALE; v.w *= QSCALE;
            __nv_bfloat16 h0,h1,h2,h3,l0,l1,l2,l3;
            split1(v.x,h0,l0); split1(v.y,h1,l1); split1(v.z,h2,l2); split1(v.w,h3,l3);
            uint32_t off = (uint32_t)(lrow * 128) + (uint32_t)((f4 * 8) ^ ((lrow & 7) << 4));
            *(uint2*)(smem + AT_QH + off) = make_uint2(pack2(h0,h1), pack2(h2,h3));
            *(uint2*)(smem + AT_QL + off) = make_uint2(pack2(l0,l1), pack2(l2,l3));
        }
    }

    // per-thread softmax state: rows (lane>>2) and (lane>>2)+8 within warp tile
    float m_i[2] = {-1e30f, -1e30f};
    float l_i[2] = {0.f, 0.f};
    float oacc[8][4];
#pragma unroll
    for (int j = 0; j < 8; j++)
#pragma unroll
        for (int q = 0; q < 4; q++) oacc[j][q] = 0.f;

    for (int kt = 0; kt <= qt; kt++) {
        __syncthreads();           // prev stage's O-MMA done; K/V/P free, Q visible
        const int k0 = kt << 6;
        // ---- load K (row-major [key][dk]) and V transposed [dk][key] -------
        {
            const float* kr = base + (long)(k0 + lrow) * 768 + 256;
            const float* vr = base + (long)(k0 + lrow) * 768 + 512;
#pragma unroll
            for (int c = 0; c < 8; c++) {
                int f4 = lhalf * 8 + c;
                float4 kv = *(const float4*)(kr + f4 * 4);
                __nv_bfloat16 h0,h1,h2,h3,l0,l1,l2,l3;
                split1(kv.x,h0,l0); split1(kv.y,h1,l1); split1(kv.z,h2,l2); split1(kv.w,h3,l3);
                uint32_t off = (uint32_t)(lrow * 128) + (uint32_t)((f4 * 8) ^ ((lrow & 7) << 4));
                *(uint2*)(smem + AT_KH + off) = make_uint2(pack2(h0,h1), pack2(h2,h3));
                *(uint2*)(smem + AT_KL + off) = make_uint2(pack2(l0,l1), pack2(l2,l3));

                float4 vv = *(const float4*)(vr + f4 * 4);
                float ve[4] = {vv.x, vv.y, vv.z, vv.w};
#pragma unroll
                for (int e = 0; e < 4; e++) {
                    int dk = f4 * 4 + e;
                    __nv_bfloat16 vh, vl;
                    split1(ve[e], vh, vl);
                    uint32_t voff = (uint32_t)(dk * 128)
                                  + (uint32_t)((lrow * 2) ^ ((dk & 7) << 4));
                    *(__nv_bfloat16*)(smem + AT_VH + voff) = vh;
                    *(__nv_bfloat16*)(smem + AT_VL + voff) = vl;
                }
            }
        }
        __syncthreads();

        // ---- S = Q K^T : warp computes m16 (its rows) x n64 (keys) ---------
        float sacc[8][4];
#pragma unroll
        for (int j = 0; j < 8; j++)
#pragma unroll
            for (int q = 0; q < 4; q++) sacc[j][q] = 0.f;

#pragma unroll
        for (int ko4 = 0; ko4 < 4; ko4++) {
            uint32_t ah[4], al[4];
            {
                int arow = w * 16 + (lane & 15);
                uint32_t acb = (uint32_t)(ko4 * 32 + ((lane >> 4) << 4));
                uint32_t aoff = (uint32_t)(arow * 128) + (acb ^ ((uint32_t)(arow & 7) << 4));
                ldsm4(ah, sb + AT_QH + aoff);
                ldsm4(al, sb + AT_QL + aoff);
            }
#pragma unroll
            for (int nj = 0; nj < 4; nj++) {
                int brow = nj * 16 + (lane & 7) + ((lane >> 4) << 3);
                uint32_t bcb = (uint32_t)(ko4 * 32 + (((lane >> 3) & 1) << 4));
                uint32_t boff = (uint32_t)(brow * 128) + (bcb ^ ((uint32_t)(brow & 7) << 4));
                uint32_t bh[4], bl[4];
                ldsm4(bh, sb + AT_KH + boff);
                ldsm4(bl, sb + AT_KL + boff);
#pragma unroll
                for (int hh = 0; hh < 2; hh++) {
                    const int j = nj * 2 + hh;
                    mma16816(sacc[j], ah, bh[hh*2], bh[hh*2+1]);
                    mma16816(sacc[j], ah, bl[hh*2], bl[hh*2+1]);
                    mma16816(sacc[j], al, bh[hh*2], bh[hh*2+1]);
                }
            }
        }

        // ---- causal mask on diagonal stage ---------------------------------
        if (kt == qt) {
            const int r0 = lane >> 2;
            const int c0 = 2 * (lane & 3);
#pragma unroll
            for (int j = 0; j < 8; j++) {
                int c = j * 8 + c0;
                int rowA = w * 16 + r0;
                int rowB = rowA + 8;
                if (c     > rowA) sacc[j][0] = -1e30f;
                if (c + 1 > rowA) sacc[j][1] = -1e30f;
                if (c     > rowB) sacc[j][2] = -1e30f;
                if (c + 1 > rowB) sacc[j][3] = -1e30f;
            }
        }

        // ---- online softmax (warp-local; rows owned by 4-lane quads) -------
#pragma unroll
        for (int rr = 0; rr < 2; rr++) {
            float mx = -1e30f;
#pragma unroll
            for (int j = 0; j < 8; j++)
                mx = fmaxf(mx, fmaxf(sacc[j][rr*2], sacc[j][rr*2+1]));
            mx = fmaxf(mx, __shfl_xor_sync(0xffffffffu, mx, 1));
            mx = fmaxf(mx, __shfl_xor_sync(0xffffffffu, mx, 2));
            float mn   = fmaxf(m_i[rr], mx);
            float corr = ex2f(m_i[rr] - mn);
            float rs = 0.f;
#pragma unroll
            for (int j = 0; j < 8; j++) {
                float p0 = ex2f(sacc[j][rr*2]   - mn);
                float p1 = ex2f(sacc[j][rr*2+1] - mn);
                sacc[j][rr*2] = p0; sacc[j][rr*2+1] = p1;
                rs += p0 + p1;
            }
            rs += __shfl_xor_sync(0xffffffffu, rs, 1);
            rs += __shfl_xor_sync(0xffffffffu, rs, 2);
            l_i[rr] = l_i[rr] * corr + rs;
            m_i[rr] = mn;
#pragma unroll
            for (int j = 0; j < 8; j++) {
                oacc[j][rr*2]   *= corr;
                oacc[j][rr*2+1] *= corr;
            }
        }

        // ---- store P h/l (row-major [q][key]; own rows only) ---------------
        {
            const int r0 = lane >> 2;
            const int c0 = 2 * (lane & 3);
#pragma unroll
            for (int rr = 0; rr < 2; rr++) {
                int row = w * 16 + r0 + rr * 8;
#pragma unroll
                for (int j = 0; j < 8; j++) {
                    int c = j * 8 + c0;
                    __nv_bfloat16 ph0, pl0, ph1, pl1;
                    split1(sacc[j][rr*2],   ph0, pl0);
                    split1(sacc[j][rr*2+1], ph1, pl1);
                    uint32_t off = (uint32_t)(row * 128)
                                 + (uint32_t)((c * 2) ^ ((row & 7) << 4));
                    *(uint32_t*)(smem + AT_PH + off) = pack2(ph0, ph1);
                    *(uint32_t*)(smem + AT_PL + off) = pack2(pl0, pl1);
                }
            }
        }
        __syncwarp();              // P produced+consumed by SAME warp only

        // ---- O += P V  (A = P rows of this warp, B = V^T [dk][key]) --------
#pragma unroll
        for (int ko4 = 0; ko4 < 4; ko4++) {
            uint32_t ph[4], pl[4];
            {
                int arow = w * 16 + (lane & 15);
                uint32_t acb = (uint32_t)(ko4 * 32 + ((lane >> 4) << 4));
                uint32_t aoff = (uint32_t)(arow * 128) + (acb ^ ((uint32_t)(arow & 7) << 4));
                ldsm4(ph, sb + AT_PH + aoff);
                ldsm4(pl, sb + AT_PL + aoff);
            }
#pragma unroll
            for (int nj = 0; nj < 4; nj++) {
                int brow = nj * 16 + (lane & 7) + ((lane >> 4) << 3);
                uint32_t bcb = (uint32_t)(ko4 * 32 + (((lane >> 3) & 1) << 4));
                uint32_t boff = (uint32_t)(brow * 128) + (bcb ^ ((uint32_t)(brow & 7) << 4));
                uint32_t vh[4], vl[4];
                ldsm4(vh, sb + AT_VH + boff);
                ldsm4(vl, sb + AT_VL + boff);
#pragma unroll
                for (int hh = 0; hh < 2; hh++) {
                    const int j = nj * 2 + hh;
                    mma16816(oacc[j], ph, vh[hh*2], vh[hh*2+1]);
                    mma16816(oacc[j], ph, vl[hh*2], vl[hh*2+1]);
                    mma16816(oacc[j], pl, vh[hh*2], vh[hh*2+1]);
                }
            }
        }
    }

    // ---- normalize and write O as bf16 hi/lo -------------------------------
#pragma unroll
    for (int rr = 0; rr < 2; rr++) {
        float inv = 1.f / l_i[rr];
        int row = w * 16 + (lane >> 2) + rr * 8;
        long gbase = (long)(b * Tn + q0 + row) * Dn + h * 64;
#pragma unroll
        for (int j = 0; j < 8; j++) {
            int c = j * 8 + 2 * (lane & 3);
            float v0 = oacc[j][rr*2]   * inv;
            float v1 = oacc[j][rr*2+1] * inv;
            __nv_bfloat16 h0, l0, h1, l1;
            split1(v0, h0, l0); split1(v1, h1, l1);
            *(__nv_bfloat162*)(g_acth + gbase + c) = __nv_bfloat162(h0, h1);
            *(__nv_bfloat162*)(g_actl + gbase + c) = __nv_bfloat162(l0, l1);
        }
    }
}

// ---------------------------------------------------------------------------
// LayerNorm: x = LN(x [+ g_tmp]) * sc + bi ; writes x fp32 AND hi/lo bf16.
// ---------------------------------------------------------------------------
template<int ADD>
__device__ __forceinline__ void ln_body(const float* __restrict__ sc,
                                        const float* __restrict__ bi)
{
    int row  = blockIdx.x * 8 + (threadIdx.x >> 5);
    int lane = threadIdx.x & 31;
    const float* pa = g_x + (long)row * Dn + lane * 8;
    float v[8];
    {
        float4 v0 = *(const float4*)pa;
        float4 v1 = *(const float4*)(pa + 4);
        v[0] = v0.x; v[1] = v0.y; v[2] = v0.z; v[3] = v0.w;
        v[4] = v1.x; v[5] = v1.y; v[6] = v1.z; v[7] = v1.w;
    }
    if (ADD) {
        const float* pr = g_tmp + (long)row * Dn + lane * 8;
        float4 r0 = *(const float4*)pr;
        float4 r1 = *(const float4*)(pr + 4);
        v[0] += r0.x; v[1] += r0.y; v[2] += r0.z; v[3] += r0.w;
        v[4] += r1.x; v[5] += r1.y; v[6] += r1.z; v[7] += r1.w;
    }
    float s = 0.f;
#pragma unroll
    for (int k = 0; k < 8; k++) s += v[k];
#pragma unroll
    for (int ofs = 16; ofs; ofs >>= 1) s += __shfl_xor_sync(0xffffffffu, s, ofs);
    float mu = s * (1.f / 256.f);
    float var = 0.f;
#pragma unroll
    for (int k = 0; k < 8; k++) { float d = v[k] - mu; var = fmaf(d, d, var); }
#pragma unroll
    for (int ofs = 16; ofs; ofs >>= 1) var += __shfl_xor_sync(0xffffffffu, var, ofs);
    float rstd = rsqrtf(var * (1.f / 256.f) + 1e-5f);

    float4 s0 = *(const float4*)(sc + lane * 8);
    float4 s1 = *(const float4*)(sc + lane * 8 + 4);
    float4 b0 = *(const float4*)(bi + lane * 8);
    float4 b1 = *(const float4*)(bi + lane * 8 + 4);
    float scv[8] = {s0.x, s0.y, s0.z, s0.w, s1.x, s1.y, s1.z, s1.w};
    float biv[8] = {b0.x, b0.y, b0.z, b0.w, b1.x, b1.y, b1.z, b1.w};
    float o[8];
    __nv_bfloat16 oh[8], ol[8];
#pragma unroll
    for (int k = 0; k < 8; k++) {
        o[k] = fmaf((v[k] - mu) * rstd, scv[k], biv[k]);
        split1(o[k], oh[k], ol[k]);
    }
    long base = (long)row * Dn + lane * 8;
    *(float4*)(g_x + base)     = make_float4(o[0], o[1], o[2], o[3]);
    *(float4*)(g_x + base + 4) = make_float4(o[4], o[5], o[6], o[7]);
#pragma unroll
    for (int k = 0; k < 4; k++) {
        ((__nv_bfloat162*)(g_acth + base))[k] = __nv_bfloat162(oh[2*k], oh[2*k+1]);
        ((__nv_bfloat162*)(g_actl + base))[k] = __nv_bfloat162(ol[2*k], ol[2*k+1]);
    }
}
__global__ void add_ln_kernel(const float* sc, const float* bi) { ln_body<1>(sc, bi); }
__global__ void final_ln_kernel(const float* sc, const float* bi) { ln_body<0>(sc, bi); }

// ---------------------------------------------------------------------------
// Orchestration
// ---------------------------------------------------------------------------
extern "C" void kernel_launch(void* const* d_in, const int* in_sizes, int n_in,
                              void* d_out, int out_size)
{
    const int*   tokens = (const int*)d_in[0];
    const float* embedw = (const float*)d_in[1];
    const float* qkv_w  = (const float*)d_in[2];
    const float* qkv_b  = (const float*)d_in[3];
    const float* fc_w   = (const float*)d_in[4];
    const float* fc_b   = (const float*)d_in[5];
    const float* ln1_s  = (const float*)d_in[6];
    const float* ln1_b  = (const float*)d_in[7];
    const float* w1     = (const float*)d_in[8];
    const float* b1     = (const float*)d_in[9];
    const float* w2     = (const float*)d_in[10];
    const float* b2     = (const float*)d_in[11];
    const float* ln2_s  = (const float*)d_in[12];
    const float* ln2_b  = (const float*)d_in[13];
    const float* lnf_s  = (const float*)d_in[14];
    const float* lnf_b  = (const float*)d_in[15];
    const float* out_w  = (const float*)d_in[16];
    const float* out_b  = (const float*)d_in[17];
    float* logits = (float*)d_out;

    cudaFuncSetAttribute((const void*)gemm_qkv_tc,
        cudaFuncAttributeMaxDynamicSharedMemorySize, GSMEM64);
    cudaFuncSetAttribute((const void*)gemm_fc_tc,
        cudaFuncAttributeMaxDynamicSharedMemorySize, GSMEM64);
    cudaFuncSetAttribute((const void*)gemm_w1_tc,
        cudaFuncAttributeMaxDynamicSharedMemorySize, GSMEM128);
    cudaFuncSetAttribute((const void*)gemm_w2_tc,
        cudaFuncAttributeMaxDynamicSharedMemorySize, GSMEM64);
    cudaFuncSetAttribute((const void*)gemm_logits_tc,
        cudaFuncAttributeMaxDynamicSharedMemorySize, GSMEM128);
    cudaFuncSetAttribute((const void*)attn_kernel,
        cudaFuncAttributeMaxDynamicSharedMemorySize, ASMEM);

    split_weights<<<2048, 256>>>(qkv_w, fc_w, w1, w2, out_w);
    embed_pos_kernel<<<Mrows, Dn>>>(tokens, embedw);

    for (int l = 0; l < 4; l++) {
        gemm_qkv_tc<<<dim3(6, 64), 256, GSMEM64>>>(l, qkv_b + l * 768);
        attn_kernel<<<dim3(32, Bn * 4), 128, ASMEM>>>();
        gemm_fc_tc<<<dim3(2, 64), 256, GSMEM64>>>(l, fc_b + l * 256);
        add_ln_kernel<<<Mrows / 8, 256>>>(ln1_s + l * 256, ln1_b + l * 256);
        gemm_w1_tc<<<dim3(8, 32), 512, GSMEM128>>>(l, b1 + l * 1024);
        gemm_w2_tc<<<dim3(2, 64), 256, GSMEM64>>>(l, b2 + l * 256);
        add_ln_kernel<<<Mrows / 8, 256>>>(ln2_s + l * 256, ln2_b + l * 256);
    }
    final_ln_kernel<<<Mrows / 8, 256>>>(lnf_s, lnf_b);
    gemm_logits_tc<<<dim3(250, 32), 512, GSMEM128>>>(out_b, logits);
}

// round 8
// speedup vs baseline: 1.6537x; 1.1438x over previous
#include <cuda_runtime.h>
#include <cuda_bf16.h>
#include <math.h>
#include <stdint.h>

// ---------------------------------------------------------------------------
// MiniGPT forward. B=2 T=2048 D=256 H=4 DK=64 DFF=1024 L=4 V=32000
// GEMMs: mma.sync bf16x3 compensated split (unchanged).
// Attention: HMMA flash, split-KV x2 + ldmatrix.trans V (no scatter), combine.
// ---------------------------------------------------------------------------

#define Tn    2048
#define Bn    2
#define Dn    256
#define Mrows 4096

// fp32 scratch
__device__ float g_x[Mrows * Dn];
__device__ float g_qkv[Mrows * 3 * Dn];
__device__ float g_tmp[Mrows * Dn];

// attention split-KV partials
__device__ float g_attp0[Mrows * Dn], g_attp1[Mrows * Dn];
__device__ float g_pm0[Mrows * 4], g_pm1[Mrows * 4];
__device__ float g_pl0[Mrows * 4], g_pl1[Mrows * 4];

// bf16 hi/lo activations (D-wide) and MLP hidden (DFF-wide)
__device__ __nv_bfloat16 g_acth[Mrows * Dn],  g_actl[Mrows * Dn];
__device__ __nv_bfloat16 g_hh[Mrows * 1024],  g_hl[Mrows * 1024];

// bf16 hi/lo weights
__device__ __nv_bfloat16 g_wqkv_h[4 * 768 * 256],  g_wqkv_l[4 * 768 * 256];
__device__ __nv_bfloat16 g_wfc_h [4 * 256 * 256],  g_wfc_l [4 * 256 * 256];
__device__ __nv_bfloat16 g_w1_h  [4 * 1024 * 256], g_w1_l  [4 * 1024 * 256];
__device__ __nv_bfloat16 g_w2_h  [4 * 256 * 1024], g_w2_l  [4 * 256 * 1024];
__device__ __nv_bfloat16 g_wout_h[32000 * 256],    g_wout_l[32000 * 256];

// ---------------------------------------------------------------------------
// PTX helpers
// ---------------------------------------------------------------------------
__device__ __forceinline__ uint32_t smem_to_u32(const void* p) {
    uint32_t a;
    asm("{ .reg .u64 t; cvta.to.shared.u64 t, %1; cvt.u32.u64 %0, t; }"
        : "=r"(a) : "l"(p));
    return a;
}
__device__ __forceinline__ void ldsm4(uint32_t* r, uint32_t addr) {
    asm volatile("ldmatrix.sync.aligned.m8n8.x4.shared.b16 {%0,%1,%2,%3}, [%4];"
                 : "=r"(r[0]), "=r"(r[1]), "=r"(r[2]), "=r"(r[3]) : "r"(addr));
}
__device__ __forceinline__ void ldsm4t(uint32_t* r, uint32_t addr) {
    asm volatile("ldmatrix.sync.aligned.m8n8.x4.trans.shared.b16 {%0,%1,%2,%3}, [%4];"
                 : "=r"(r[0]), "=r"(r[1]), "=r"(r[2]), "=r"(r[3]) : "r"(addr));
}
__device__ __forceinline__ void mma16816(float* d, const uint32_t* a,
                                         uint32_t b0, uint32_t b1) {
    asm volatile(
        "mma.sync.aligned.m16n8k16.row.col.f32.bf16.bf16.f32 "
        "{%0,%1,%2,%3}, {%4,%5,%6,%7}, {%8,%9}, {%0,%1,%2,%3};"
        : "+f"(d[0]), "+f"(d[1]), "+f"(d[2]), "+f"(d[3])
        : "r"(a[0]), "r"(a[1]), "r"(a[2]), "r"(a[3]), "r"(b0), "r"(b1));
}
__device__ __forceinline__ float ex2f(float x) {
    float y;
    asm("ex2.approx.f32 %0, %1;" : "=f"(y) : "f"(x));
    return y;
}
#define CP_ASYNC16(dst, src) \
    asm volatile("cp.async.cg.shared.global [%0], [%1], 16;" \
                 :: "r"(dst), "l"(src) : "memory")
#define CP_COMMIT()  asm volatile("cp.async.commit_group;" ::: "memory")
#define CP_WAIT0()   asm volatile("cp.async.wait_group 0;" ::: "memory")

__device__ __forceinline__ void split1(float v, __nv_bfloat16& h, __nv_bfloat16& l) {
    h = __float2bfloat16(v);
    l = __float2bfloat16(v - __bfloat162float(h));
}
__device__ __forceinline__ uint32_t pack2(__nv_bfloat16 a, __nv_bfloat16 b) {
    __nv_bfloat162 t(a, b);
    return *(uint32_t*)&t;
}

// ---------------------------------------------------------------------------
// Fused weight split
// ---------------------------------------------------------------------------
__global__ void split_weights(const float* __restrict__ qkv_w,
                              const float* __restrict__ fc_w,
                              const float* __restrict__ w1,
                              const float* __restrict__ w2,
                              const float* __restrict__ out_w)
{
    const int c0 = 196608, c1 = c0 + 65536, c2 = c1 + 262144,
              c3 = c2 + 262144, c4 = c3 + 2048000;
    int stride = gridDim.x * blockDim.x;
    for (int idx = blockIdx.x * blockDim.x + threadIdx.x; idx < c4; idx += stride) {
        const float* src; __nv_bfloat16 *dh, *dl; int li;
        if (idx < c0)      { src = qkv_w; dh = g_wqkv_h; dl = g_wqkv_l; li = idx; }
        else if (idx < c1) { src = fc_w;  dh = g_wfc_h;  dl = g_wfc_l;  li = idx - c0; }
        else if (idx < c2) { src = w1;    dh = g_w1_h;   dl = g_w1_l;   li = idx - c1; }
        else if (idx < c3) { src = w2;    dh = g_w2_h;   dl = g_w2_l;   li = idx - c2; }
        else               { src = out_w; dh = g_wout_h; dl = g_wout_l; li = idx - c3; }
        float4 v = ((const float4*)src)[li];
        __nv_bfloat16 h0, h1, h2, h3, l0, l1, l2, l3;
        split1(v.x, h0, l0); split1(v.y, h1, l1);
        split1(v.z, h2, l2); split1(v.w, h3, l3);
        ((__nv_bfloat162*)dh)[li * 2 + 0] = __nv_bfloat162(h0, h1);
        ((__nv_bfloat162*)dh)[li * 2 + 1] = __nv_bfloat162(h2, h3);
        ((__nv_bfloat162*)dl)[li * 2 + 0] = __nv_bfloat162(l0, l1);
        ((__nv_bfloat162*)dl)[li * 2 + 1] = __nv_bfloat162(l2, l3);
    }
}

// ---------------------------------------------------------------------------
// mma.sync bf16x3 GEMM (unchanged)
// ---------------------------------------------------------------------------
#define GSMEM128 (2 * 65536)
#define GSMEM64  (2 * 49152)

template<int TM, int N, int K, int RELU, int WSPLIT>
__device__ __forceinline__ void gemm_body(
    const __nv_bfloat16* __restrict__ Ah, const __nv_bfloat16* __restrict__ Al,
    const __nv_bfloat16* __restrict__ Bh, const __nv_bfloat16* __restrict__ Bl,
    const float* __restrict__ bias, float* __restrict__ C,
    __nv_bfloat16* __restrict__ Ch, __nv_bfloat16* __restrict__ Cl)
{
    extern __shared__ char smem[];
    const uint32_t sb = smem_to_u32(smem);
    const int tid  = threadIdx.x;
    const int wid  = tid >> 5;
    const int lane = tid & 31;
    const int m0   = blockIdx.y * TM;
    const int n0   = blockIdx.x << 7;
    constexpr int NST   = K / 64;
    constexpr int STAGE = (TM == 128) ? 65536 : 49152;
    constexpr int AOFF  = (TM == 128) ? 16384 : 8192;
    constexpr int BOFF  = (TM == 128) ? 32768 : 16384;
    constexpr int BSZ   = 16384;
    const int wr = (TM == 128) ? (wid & 3) : (wid & 1);
    const int wc = (TM == 128) ? (wid >> 2) : (wid >> 1);

    float acc[2][4][4];
#pragma unroll
    for (int i = 0; i < 2; i++)
#pragma unroll
        for (int j = 0; j < 4; j++)
#pragma unroll
            for (int q = 0; q < 4; q++) acc[i][j][q] = 0.f;

    const __nv_bfloat16 *gp128 = nullptr;
    uint32_t dst128 = 0, sw128v = 0;
    const __nv_bfloat16 *pah = nullptr, *pal = nullptr, *pbh = nullptr, *pbl = nullptr;
    uint32_t dq = 0, swq = 0;
    if (TM == 128) {
        const int lr = tid & 127;
        const int lt = tid >> 7;
        gp128 = (lt == 0) ? Ah + (long)(m0 + lr) * K :
                (lt == 1) ? Al + (long)(m0 + lr) * K :
                (lt == 2) ? Bh + (long)(n0 + lr) * K :
                            Bl + (long)(n0 + lr) * K;
        dst128 = sb + lt * 16384 + lr * 128;
        sw128v = (uint32_t)((lr & 7) << 4);
    } else {
        const int q = tid >> 3;
        uint32_t cbyte = (uint32_t)((tid & 7) << 4);
        swq   = cbyte ^ (uint32_t)((q & 7) << 4);
        dq    = (uint32_t)q;
        const int ce = (tid & 7) << 3;
        pah = Ah + (long)(m0 + q) * K + ce;
        pal = Al + (long)(m0 + q) * K + ce;
        pbh = Bh + (long)(n0 + q) * K + ce;
        pbl = Bl + (long)(n0 + q) * K + ce;
    }

#define LOAD_STAGE(sbuf, koff)                                                  \
    do {                                                                        \
        if (TM == 128) {                                                        \
            const char* src = (const char*)(gp128 + (koff));                    \
            uint32_t db = dst128 + (sbuf) * (uint32_t)STAGE;                    \
            _Pragma("unroll")                                                   \
            for (int c = 0; c < 8; c++)                                         \
                CP_ASYNC16(db + (uint32_t)((c * 16) ^ sw128v), src + c * 16);   \
        } else {                                                                \
            uint32_t base = sb + (sbuf) * (uint32_t)STAGE;                      \
            _Pragma("unroll")                                                   \
            for (int u = 0; u < 2; u++) {                                       \
                uint32_t row = dq + u * 32;                                     \
                CP_ASYNC16(base + row * 128 + swq,                              \
                           (const char*)(pah + (long)u * 32 * K + (koff)));     \
                CP_ASYNC16(base + AOFF + row * 128 + swq,                       \
                           (const char*)(pal + (long)u * 32 * K + (koff)));     \
            }                                                                   \
            _Pragma("unroll")                                                   \
            for (int u = 0; u < 4; u++) {                                       \
                uint32_t row = dq + u * 32;                                     \
                CP_ASYNC16(base + BOFF + row * 128 + swq,                       \
                           (const char*)(pbh + (long)u * 32 * K + (koff)));     \
                CP_ASYNC16(base + BOFF + BSZ + row * 128 + swq,                 \
                           (const char*)(pbl + (long)u * 32 * K + (koff)));     \
            }                                                                   \
        }                                                                       \
        CP_COMMIT();                                                            \
    } while (0)

    LOAD_STAGE(0, 0);

    for (int s = 0; s < NST; s++) {
        CP_WAIT0();
        __syncthreads();
        if (s + 1 < NST) LOAD_STAGE((s + 1) & 1, (s + 1) * 64);
        const uint32_t bufb = sb + (uint32_t)((s & 1) * STAGE);

#pragma unroll
        for (int ko = 0; ko < 64; ko += 16) {
            uint32_t afr[2][2][4];
            uint32_t bfr[2][2][4];
            {
                const int rowb = wr * 32 + (lane & 15);
                const int cb   = ko * 2 + ((lane >> 4) << 4);
#pragma unroll
                for (int t = 0; t < 2; t++)
#pragma unroll
                    for (int mi = 0; mi < 2; mi++) {
                        int row = rowb + mi * 16;
                        uint32_t addr = bufb + (uint32_t)(t * AOFF) + row * 128
                                      + (uint32_t)(cb ^ ((row & 7) << 4));
                        ldsm4(afr[t][mi], addr);
                    }
            }
            {
                const int rowb = wc * 32 + (lane & 7) + ((lane >> 4) << 3);
                const int cb   = ko * 2 + (((lane >> 3) & 1) << 4);
#pragma unroll
                for (int t = 0; t < 2; t++)
#pragma unroll
                    for (int nj = 0; nj < 2; nj++) {
                        int row = rowb + nj * 16;
                        uint32_t addr = bufb + (uint32_t)BOFF + (uint32_t)(t * BSZ)
                                      + row * 128 + (uint32_t)(cb ^ ((row & 7) << 4));
                        ldsm4(bfr[t][nj], addr);
                    }
            }
#pragma unroll
            for (int mi = 0; mi < 2; mi++)
#pragma unroll
                for (int nj = 0; nj < 2; nj++)
#pragma unroll
                    for (int hh = 0; hh < 2; hh++) {
                        const int nc = nj * 2 + hh;
                        const uint32_t bh0 = bfr[0][nj][hh * 2];
                        const uint32_t bh1 = bfr[0][nj][hh * 2 + 1];
                        const uint32_t bl0 = bfr[1][nj][hh * 2];
                        const uint32_t bl1 = bfr[1][nj][hh * 2 + 1];
                        mma16816(acc[mi][nc], afr[0][mi], bh0, bh1);
                        mma16816(acc[mi][nc], afr[0][mi], bl0, bl1);
                        mma16816(acc[mi][nc], afr[1][mi], bh0, bh1);
                    }
        }
        __syncthreads();
    }
#undef LOAD_STAGE

#pragma unroll
    for (int mi = 0; mi < 2; mi++)
#pragma unroll
        for (int nc = 0; nc < 4; nc++) {
            int row = m0 + wr * 32 + mi * 16 + (lane >> 2);
            int col = n0 + wc * 32 + nc * 8 + (lane & 3) * 2;
            float b0v = bias[col], b1v = bias[col + 1];
            float v0 = acc[mi][nc][0] + b0v;
            float v1 = acc[mi][nc][1] + b1v;
            float v2 = acc[mi][nc][2] + b0v;
            float v3 = acc[mi][nc][3] + b1v;
            if (RELU) {
                v0 = fmaxf(v0, 0.f); v1 = fmaxf(v1, 0.f);
                v2 = fmaxf(v2, 0.f); v3 = fmaxf(v3, 0.f);
            }
            if (WSPLIT) {
                __nv_bfloat16 h0, h1, h2, h3, l0, l1, l2, l3;
                split1(v0, h0, l0); split1(v1, h1, l1);
                split1(v2, h2, l2); split1(v3, h3, l3);
                *(__nv_bfloat162*)(Ch + (long)row * N + col)       = __nv_bfloat162(h0, h1);
                *(__nv_bfloat162*)(Ch + (long)(row + 8) * N + col) = __nv_bfloat162(h2, h3);
                *(__nv_bfloat162*)(Cl + (long)row * N + col)       = __nv_bfloat162(l0, l1);
                *(__nv_bfloat162*)(Cl + (long)(row + 8) * N + col) = __nv_bfloat162(l2, l3);
            } else {
                *(float2*)(C + (long)row * N + col)       = make_float2(v0, v1);
                *(float2*)(C + (long)(row + 8) * N + col) = make_float2(v2, v3);
            }
        }
}

__global__ __launch_bounds__(256) void gemm_qkv_tc(int l, const float* bias)
{ gemm_body<64, 768, 256, 0, 0>(g_acth, g_actl, g_wqkv_h + l*196608, g_wqkv_l + l*196608,
                                bias, g_qkv, nullptr, nullptr); }
__global__ __launch_bounds__(256) void gemm_fc_tc(int l, const float* bias)
{ gemm_body<64, 256, 256, 0, 0>(g_acth, g_actl, g_wfc_h + l*65536, g_wfc_l + l*65536,
                                bias, g_tmp, nullptr, nullptr); }
__global__ __launch_bounds__(512) void gemm_w1_tc(int l, const float* bias)
{ gemm_body<128, 1024, 256, 1, 1>(g_acth, g_actl, g_w1_h + l*262144, g_w1_l + l*262144,
                                  bias, nullptr, g_hh, g_hl); }
__global__ __launch_bounds__(256) void gemm_w2_tc(int l, const float* bias)
{ gemm_body<64, 256, 1024, 0, 0>(g_hh, g_hl, g_w2_h + l*262144, g_w2_l + l*262144,
                                 bias, g_tmp, nullptr, nullptr); }
__global__ __launch_bounds__(512) void gemm_logits_tc(const float* bias, float* out)
{ gemm_body<128, 32000, 256, 0, 0>(g_acth, g_actl, g_wout_h, g_wout_l,
                                   bias, out, nullptr, nullptr); }

// ---------------------------------------------------------------------------
// Embedding + positional encoding
// ---------------------------------------------------------------------------
__global__ void embed_pos_kernel(const int* __restrict__ tok,
                                 const float* __restrict__ emb)
{
    int row = blockIdx.x;
    int d   = threadIdx.x;
    int t   = row & (Tn - 1);
    int token = tok[row];
    double div = exp(-(double)(d & ~1) * (9.210340371976184 / 256.0));
    double ang = (double)t * div;
    float  pe  = (d & 1) ? (float)cos(ang) : (float)sin(ang);
    float v = emb[token * Dn + d] + pe;
    g_x[row * Dn + d] = v;
    __nv_bfloat16 h, l;
    split1(v, h, l);
    g_acth[row * Dn + d] = h;
    g_actl[row * Dn + d] = l;
}

// ---------------------------------------------------------------------------
// HMMA flash attention, split-KV x2. Block = 128 thr / 4 warps; q-tile 64.
// half = blockIdx.z processes kt = half, half+2, ... <= qt (max 16 iters).
// V stored ROW-major (like K); PV B-operand via ldmatrix.trans.
// Partials (unnormalized O, m, l) -> global; combined by attn_combine.
// smem: Qh 0 | Ql 8K | Kh 16K | Kl 24K | Vh 32K | Vl 40K | Ph 48K | Pl 56K.
// ---------------------------------------------------------------------------
#define AT_QH 0
#define AT_QL 8192
#define AT_KH 16384
#define AT_KL 24576
#define AT_VH 32768
#define AT_VL 40960
#define AT_PH 49152
#define AT_PL 57344
#define ASMEM 65536
#define QSCALE 0.18033688f    /* 0.125 * log2(e) */

__global__ __launch_bounds__(128) void attn_kernel()
{
    extern __shared__ char smem[];
    const uint32_t sb = smem_to_u32(smem);
    const int tid  = threadIdx.x;
    const int lane = tid & 31;
    const int w    = tid >> 5;
    const int qt   = blockIdx.x;
    const int b    = blockIdx.y >> 2;
    const int h    = blockIdx.y & 3;
    const int half = blockIdx.z;
    const int q0   = qt << 6;
    const float* base = g_qkv + (long)b * Tn * 768 + h * 64;

    const int lrow  = tid & 63;
    const int lhalf = tid >> 6;

    // ---- load Q (scaled, split h/l, row-major [q][dk]) ---------------------
    {
        const float* qr = base + (long)(q0 + lrow) * 768;
#pragma unroll
        for (int c = 0; c < 8; c++) {
            int f4 = lhalf * 8 + c;
            float4 v = *(const float4*)(qr + f4 * 4);
            v.x *= QSCALE; v.y *= QSCALE; v.z *= QSCALE; v.w *= QSCALE;
            __nv_bfloat16 h0,h1,h2,h3,l0,l1,l2,l3;
            split1(v.x,h0,l0); split1(v.y,h1,l1); split1(v.z,h2,l2); split1(v.w,h3,l3);
            uint32_t off = (uint32_t)(lrow * 128) + (uint32_t)((f4 * 8) ^ ((lrow & 7) << 4));
            *(uint2*)(smem + AT_QH + off) = make_uint2(pack2(h0,h1), pack2(h2,h3));
            *(uint2*)(smem + AT_QL + off) = make_uint2(pack2(l0,l1), pack2(l2,l3));
        }
    }

    float m_i[2] = {-1e30f, -1e30f};
    float l_i[2] = {0.f, 0.f};
    float oacc[8][4];
#pragma unroll
    for (int j = 0; j < 8; j++)
#pragma unroll
        for (int q = 0; q < 4; q++) oacc[j][q] = 0.f;

    for (int kt = half; kt <= qt; kt += 2) {
        __syncthreads();
        const int k0 = kt << 6;
        // ---- load K and V, both row-major [key][dk] ------------------------
        {
            const float* kr = base + (long)(k0 + lrow) * 768 + 256;
            const float* vr = base + (long)(k0 + lrow) * 768 + 512;
#pragma unroll
            for (int c = 0; c < 8; c++) {
                int f4 = lhalf * 8 + c;
                uint32_t off = (uint32_t)(lrow * 128) + (uint32_t)((f4 * 8) ^ ((lrow & 7) << 4));
                float4 kv = *(const float4*)(kr + f4 * 4);
                __nv_bfloat16 h0,h1,h2,h3,l0,l1,l2,l3;
                split1(kv.x,h0,l0); split1(kv.y,h1,l1); split1(kv.z,h2,l2); split1(kv.w,h3,l3);
                *(uint2*)(smem + AT_KH + off) = make_uint2(pack2(h0,h1), pack2(h2,h3));
                *(uint2*)(smem + AT_KL + off) = make_uint2(pack2(l0,l1), pack2(l2,l3));
                float4 vv = *(const float4*)(vr + f4 * 4);
                split1(vv.x,h0,l0); split1(vv.y,h1,l1); split1(vv.z,h2,l2); split1(vv.w,h3,l3);
                *(uint2*)(smem + AT_VH + off) = make_uint2(pack2(h0,h1), pack2(h2,h3));
                *(uint2*)(smem + AT_VL + off) = make_uint2(pack2(l0,l1), pack2(l2,l3));
            }
        }
        __syncthreads();

        // ---- S = Q K^T -----------------------------------------------------
        float sacc[8][4];
#pragma unroll
        for (int j = 0; j < 8; j++)
#pragma unroll
            for (int q = 0; q < 4; q++) sacc[j][q] = 0.f;

#pragma unroll
        for (int ko4 = 0; ko4 < 4; ko4++) {
            uint32_t ah[4], al[4];
            {
                int arow = w * 16 + (lane & 15);
                uint32_t acb = (uint32_t)(ko4 * 32 + ((lane >> 4) << 4));
                uint32_t aoff = (uint32_t)(arow * 128) + (acb ^ ((uint32_t)(arow & 7) << 4));
                ldsm4(ah, sb + AT_QH + aoff);
                ldsm4(al, sb + AT_QL + aoff);
            }
#pragma unroll
            for (int nj = 0; nj < 4; nj++) {
                int brow = nj * 16 + (lane & 7) + ((lane >> 4) << 3);
                uint32_t bcb = (uint32_t)(ko4 * 32 + (((lane >> 3) & 1) << 4));
                uint32_t boff = (uint32_t)(brow * 128) + (bcb ^ ((uint32_t)(brow & 7) << 4));
                uint32_t bh[4], bl[4];
                ldsm4(bh, sb + AT_KH + boff);
                ldsm4(bl, sb + AT_KL + boff);
#pragma unroll
                for (int hh = 0; hh < 2; hh++) {
                    const int j = nj * 2 + hh;
                    mma16816(sacc[j], ah, bh[hh*2], bh[hh*2+1]);
                    mma16816(sacc[j], ah, bl[hh*2], bl[hh*2+1]);
                    mma16816(sacc[j], al, bh[hh*2], bh[hh*2+1]);
                }
            }
        }

        // ---- causal mask on diagonal ---------------------------------------
        if (kt == qt) {
            const int r0 = lane >> 2;
            const int c0 = 2 * (lane & 3);
#pragma unroll
            for (int j = 0; j < 8; j++) {
                int c = j * 8 + c0;
                int rowA = w * 16 + r0;
                int rowB = rowA + 8;
                if (c     > rowA) sacc[j][0] = -1e30f;
                if (c + 1 > rowA) sacc[j][1] = -1e30f;
                if (c     > rowB) sacc[j][2] = -1e30f;
                if (c + 1 > rowB) sacc[j][3] = -1e30f;
            }
        }

        // ---- online softmax (warp-local) -----------------------------------
#pragma unroll
        for (int rr = 0; rr < 2; rr++) {
            float mx = -1e30f;
#pragma unroll
            for (int j = 0; j < 8; j++)
                mx = fmaxf(mx, fmaxf(sacc[j][rr*2], sacc[j][rr*2+1]));
            mx = fmaxf(mx, __shfl_xor_sync(0xffffffffu, mx, 1));
            mx = fmaxf(mx, __shfl_xor_sync(0xffffffffu, mx, 2));
            float mn   = fmaxf(m_i[rr], mx);
            float corr = ex2f(m_i[rr] - mn);
            float rs = 0.f;
#pragma unroll
            for (int j = 0; j < 8; j++) {
                float p0 = ex2f(sacc[j][rr*2]   - mn);
                float p1 = ex2f(sacc[j][rr*2+1] - mn);
                sacc[j][rr*2] = p0; sacc[j][rr*2+1] = p1;
                rs += p0 + p1;
            }
            rs += __shfl_xor_sync(0xffffffffu, rs, 1);
            rs += __shfl_xor_sync(0xffffffffu, rs, 2);
            l_i[rr] = l_i[rr] * corr + rs;
            m_i[rr] = mn;
#pragma unroll
            for (int j = 0; j < 8; j++) {
                oacc[j][rr*2]   *= corr;
                oacc[j][rr*2+1] *= corr;
            }
        }

        // ---- store P h/l (row-major [q][key]) ------------------------------
        {
            const int r0 = lane >> 2;
            const int c0 = 2 * (lane & 3);
#pragma unroll
            for (int rr = 0; rr < 2; rr++) {
                int row = w * 16 + r0 + rr * 8;
#pragma unroll
                for (int j = 0; j < 8; j++) {
                    int c = j * 8 + c0;
                    __nv_bfloat16 ph0, pl0, ph1, pl1;
                    split1(sacc[j][rr*2],   ph0, pl0);
                    split1(sacc[j][rr*2+1], ph1, pl1);
                    uint32_t off = (uint32_t)(row * 128)
                                 + (uint32_t)((c * 2) ^ ((row & 7) << 4));
                    *(uint32_t*)(smem + AT_PH + off) = pack2(ph0, ph1);
                    *(uint32_t*)(smem + AT_PL + off) = pack2(pl0, pl1);
                }
            }
        }
        __syncwarp();

        // ---- O += P V : B = V^T via ldmatrix.trans on row-major V ----------
#pragma unroll
        for (int ko4 = 0; ko4 < 4; ko4++) {
            uint32_t ph[4], pl[4];
            {
                int arow = w * 16 + (lane & 15);
                uint32_t acb = (uint32_t)(ko4 * 32 + ((lane >> 4) << 4));
                uint32_t aoff = (uint32_t)(arow * 128) + (acb ^ ((uint32_t)(arow & 7) << 4));
                ldsm4(ph, sb + AT_PH + aoff);
                ldsm4(pl, sb + AT_PL + aoff);
            }
#pragma unroll
            for (int nj = 0; nj < 4; nj++) {
                // trans: stored row = key, byte col = dk
                int brow = ko4 * 16 + (lane & 7) + (((lane >> 3) & 1) << 3);
                uint32_t bcb = (uint32_t)(nj * 32 + ((lane >> 4) << 4));
                uint32_t boff = (uint32_t)(brow * 128) + (bcb ^ ((uint32_t)(brow & 7) << 4));
                uint32_t vh[4], vl[4];
                ldsm4t(vh, sb + AT_VH + boff);
                ldsm4t(vl, sb + AT_VL + boff);
#pragma unroll
                for (int hh = 0; hh < 2; hh++) {
                    const int j = nj * 2 + hh;
                    mma16816(oacc[j], ph, vh[hh*2], vh[hh*2+1]);
                    mma16816(oacc[j], ph, vl[hh*2], vl[hh*2+1]);
                    mma16816(oacc[j], pl, vh[hh*2], vh[hh*2+1]);
                }
            }
        }
    }

    // ---- write partials (unnormalized O, m, l) -----------------------------
    float* attp = half ? g_attp1 : g_attp0;
    float* pm   = half ? g_pm1   : g_pm0;
    float* pl_  = half ? g_pl1   : g_pl0;
#pragma unroll
    for (int rr = 0; rr < 2; rr++) {
        int row  = w * 16 + (lane >> 2) + rr * 8;
        int grow = b * Tn + q0 + row;
        long gbase = (long)grow * Dn + h * 64;
#pragma unroll
        for (int j = 0; j < 8; j++) {
            int c = j * 8 + 2 * (lane & 3);
            *(float2*)(attp + gbase + c) = make_float2(oacc[j][rr*2], oacc[j][rr*2+1]);
        }
        if ((lane & 3) == 0) {
            pm [grow * 4 + h] = m_i[rr];
            pl_[grow * 4 + h] = l_i[rr];
        }
    }
}

// ---------------------------------------------------------------------------
// Combine split-KV halves -> bf16 hi/lo activations.
// 1 thread per 4 dk: 4096*64 threads.
// ---------------------------------------------------------------------------
__global__ void attn_combine()
{
    int idx = blockIdx.x * 256 + threadIdx.x;   // 0 .. 262143
    int row = idx >> 6;
    int dq  = (idx & 63) << 2;
    int h   = dq >> 6;
    float m0 = g_pm0[row * 4 + h], m1 = g_pm1[row * 4 + h];
    float l0 = g_pl0[row * 4 + h], l1 = g_pl1[row * 4 + h];
    float m  = fmaxf(m0, m1);
    float c0 = ex2f(m0 - m), c1 = ex2f(m1 - m);
    float inv = 1.f / fmaf(l0, c0, l1 * c1);
    float4 p0 = *(float4*)(g_attp0 + (long)row * Dn + dq);
    float4 p1 = *(float4*)(g_attp1 + (long)row * Dn + dq);
    float v0 = fmaf(p0.x, c0, p1.x * c1) * inv;
    float v1 = fmaf(p0.y, c0, p1.y * c1) * inv;
    float v2 = fmaf(p0.z, c0, p1.z * c1) * inv;
    float v3 = fmaf(p0.w, c0, p1.w * c1) * inv;
    __nv_bfloat16 h0,h1,h2,h3,l0b,l1b,l2b,l3b;
    split1(v0,h0,l0b); split1(v1,h1,l1b); split1(v2,h2,l2b); split1(v3,h3,l3b);
    long base = (long)row * Dn + dq;
    *(__nv_bfloat162*)(g_acth + base)     = __nv_bfloat162(h0, h1);
    *(__nv_bfloat162*)(g_acth + base + 2) = __nv_bfloat162(h2, h3);
    *(__nv_bfloat162*)(g_actl + base)     = __nv_bfloat162(l0b, l1b);
    *(__nv_bfloat162*)(g_actl + base + 2) = __nv_bfloat162(l2b, l3b);
}

// ---------------------------------------------------------------------------
// LayerNorm: x = LN(x [+ g_tmp]) * sc + bi ; writes x fp32 AND hi/lo bf16.
// ---------------------------------------------------------------------------
template<int ADD>
__device__ __forceinline__ void ln_body(const float* __restrict__ sc,
                                        const float* __restrict__ bi)
{
    int row  = blockIdx.x * 8 + (threadIdx.x >> 5);
    int lane = threadIdx.x & 31;
    const float* pa = g_x + (long)row * Dn + lane * 8;
    float v[8];
    {
        float4 v0 = *(const float4*)pa;
        float4 v1 = *(const float4*)(pa + 4);
        v[0] = v0.x; v[1] = v0.y; v[2] = v0.z; v[3] = v0.w;
        v[4] = v1.x; v[5] = v1.y; v[6] = v1.z; v[7] = v1.w;
    }
    if (ADD) {
        const float* pr = g_tmp + (long)row * Dn + lane * 8;
        float4 r0 = *(const float4*)pr;
        float4 r1 = *(const float4*)(pr + 4);
        v[0] += r0.x; v[1] += r0.y; v[2] += r0.z; v[3] += r0.w;
        v[4] += r1.x; v[5] += r1.y; v[6] += r1.z; v[7] += r1.w;
    }
    float s = 0.f;
#pragma unroll
    for (int k = 0; k < 8; k++) s += v[k];
#pragma unroll
    for (int ofs = 16; ofs; ofs >>= 1) s += __shfl_xor_sync(0xffffffffu, s, ofs);
    float mu = s * (1.f / 256.f);
    float var = 0.f;
#pragma unroll
    for (int k = 0; k < 8; k++) { float d = v[k] - mu; var = fmaf(d, d, var); }
#pragma unroll
    for (int ofs = 16; ofs; ofs >>= 1) var += __shfl_xor_sync(0xffffffffu, var, ofs);
    float rstd = rsqrtf(var * (1.f / 256.f) + 1e-5f);

    float4 s0 = *(const float4*)(sc + lane * 8);
    float4 s1 = *(const float4*)(sc + lane * 8 + 4);
    float4 b0 = *(const float4*)(bi + lane * 8);
    float4 b1 = *(const float4*)(bi + lane * 8 + 4);
    float scv[8] = {s0.x, s0.y, s0.z, s0.w, s1.x, s1.y, s1.z, s1.w};
    float biv[8] = {b0.x, b0.y, b0.z, b0.w, b1.x, b1.y, b1.z, b1.w};
    float o[8];
    __nv_bfloat16 oh[8], ol[8];
#pragma unroll
    for (int k = 0; k < 8; k++) {
        o[k] = fmaf((v[k] - mu) * rstd, scv[k], biv[k]);
        split1(o[k], oh[k], ol[k]);
    }
    long base = (long)row * Dn + lane * 8;
    *(float4*)(g_x + base)     = make_float4(o[0], o[1], o[2], o[3]);
    *(float4*)(g_x + base + 4) = make_float4(o[4], o[5], o[6], o[7]);
#pragma unroll
    for (int k = 0; k < 4; k++) {
        ((__nv_bfloat162*)(g_acth + base))[k] = __nv_bfloat162(oh[2*k], oh[2*k+1]);
        ((__nv_bfloat162*)(g_actl + base))[k] = __nv_bfloat162(ol[2*k], ol[2*k+1]);
    }
}
__global__ void add_ln_kernel(const float* sc, const float* bi) { ln_body<1>(sc, bi); }
__global__ void final_ln_kernel(const float* sc, const float* bi) { ln_body<0>(sc, bi); }

// ---------------------------------------------------------------------------
// Orchestration
// ---------------------------------------------------------------------------
extern "C" void kernel_launch(void* const* d_in, const int* in_sizes, int n_in,
                              void* d_out, int out_size)
{
    const int*   tokens = (const int*)d_in[0];
    const float* embedw = (const float*)d_in[1];
    const float* qkv_w  = (const float*)d_in[2];
    const float* qkv_b  = (const float*)d_in[3];
    const float* fc_w   = (const float*)d_in[4];
    const float* fc_b   = (const float*)d_in[5];
    const float* ln1_s  = (const float*)d_in[6];
    const float* ln1_b  = (const float*)d_in[7];
    const float* w1     = (const float*)d_in[8];
    const float* b1     = (const float*)d_in[9];
    const float* w2     = (const float*)d_in[10];
    const float* b2     = (const float*)d_in[11];
    const float* ln2_s  = (const float*)d_in[12];
    const float* ln2_b  = (const float*)d_in[13];
    const float* lnf_s  = (const float*)d_in[14];
    const float* lnf_b  = (const float*)d_in[15];
    const float* out_w  = (const float*)d_in[16];
    const float* out_b  = (const float*)d_in[17];
    float* logits = (float*)d_out;

    cudaFuncSetAttribute((const void*)gemm_qkv_tc,
        cudaFuncAttributeMaxDynamicSharedMemorySize, GSMEM64);
    cudaFuncSetAttribute((const void*)gemm_fc_tc,
        cudaFuncAttributeMaxDynamicSharedMemorySize, GSMEM64);
    cudaFuncSetAttribute((const void*)gemm_w1_tc,
        cudaFuncAttributeMaxDynamicSharedMemorySize, GSMEM128);
    cudaFuncSetAttribute((const void*)gemm_w2_tc,
        cudaFuncAttributeMaxDynamicSharedMemorySize, GSMEM64);
    cudaFuncSetAttribute((const void*)gemm_logits_tc,
        cudaFuncAttributeMaxDynamicSharedMemorySize, GSMEM128);
    cudaFuncSetAttribute((const void*)attn_kernel,
        cudaFuncAttributeMaxDynamicSharedMemorySize, ASMEM);

    split_weights<<<2048, 256>>>(qkv_w, fc_w, w1, w2, out_w);
    embed_pos_kernel<<<Mrows, Dn>>>(tokens, embedw);

    for (int l = 0; l < 4; l++) {
        gemm_qkv_tc<<<dim3(6, 64), 256, GSMEM64>>>(l, qkv_b + l * 768);
        attn_kernel<<<dim3(32, Bn * 4, 2), 128, ASMEM>>>();
        attn_combine<<<1024, 256>>>();
        gemm_fc_tc<<<dim3(2, 64), 256, GSMEM64>>>(l, fc_b + l * 256);
        add_ln_kernel<<<Mrows / 8, 256>>>(ln1_s + l * 256, ln1_b + l * 256);
        gemm_w1_tc<<<dim3(8, 32), 512, GSMEM128>>>(l, b1 + l * 1024);
        gemm_w2_tc<<<dim3(2, 64), 256, GSMEM64>>>(l, b2 + l * 256);
        add_ln_kernel<<<Mrows / 8, 256>>>(ln2_s + l * 256, ln2_b + l * 256);
    }
    final_ln_kernel<<<Mrows / 8, 256>>>(lnf_s, lnf_b);
    gemm_logits_tc<<<dim3(250, 32), 512, GSMEM128>>>(out_b, logits);
}